// round 4
// baseline (speedup 1.0000x reference)
#include <cuda_runtime.h>
#include <math.h>

#define BB 4
#define SS 2048
#define EE 1024
#define FF 3072   // 3*EE

// Scratch for fused QKV projection output: [B*S, 3E] = 8192 x 3072 floats (~100MB)
__device__ float g_qkv[(size_t)BB * SS * FF];

// ---------------------------------------------------------------------------
// Tiled SGEMM: C = alpha * A @ op(B) (+ bias), 128x128x8 tiles, 8x8 per thread.
// TRANSB=true : B is [N, K] row-major  (C = A @ B^T)
// TRANSB=false: B is [K, N] row-major  (C = A @ B)
// All of M, N divisible by 128; K divisible by 8. Row strides lda/ldb/ldc.
// blockIdx.z = batch index with element strides sA/sB/sC.
// ---------------------------------------------------------------------------
template <bool TRANSB>
__global__ __launch_bounds__(256, 2) void sgemm_kernel(
    const float* __restrict__ A, const float* __restrict__ Bm,
    float* __restrict__ C,
    int M, int N, int K, int lda, int ldb, int ldc,
    size_t sA, size_t sB, size_t sC,
    const float* __restrict__ bias, float alpha)
{
    A  += sA * (size_t)blockIdx.z;
    Bm += sB * (size_t)blockIdx.z;
    C  += sC * (size_t)blockIdx.z;

    __shared__ float As[8][132];   // [k][m], padded to break store conflicts
    __shared__ float Bs[8][132];   // [k][n]

    const int tid = threadIdx.x;          // 0..255
    const int tx  = tid & 15;             // 0..15  (n direction)
    const int ty  = tid >> 4;             // 0..15  (m direction)

    const int m0 = blockIdx.y * 128;
    const int n0 = blockIdx.x * 128;

    // A-load mapping: each thread loads one float4. row = tid/2, k-chunk = tid%2.
    const int a_row = tid >> 1;
    const int a_k4  = (tid & 1) * 4;

    float acc[8][8];
#pragma unroll
    for (int i = 0; i < 8; i++)
#pragma unroll
        for (int j = 0; j < 8; j++) acc[i][j] = 0.0f;

    for (int k0 = 0; k0 < K; k0 += 8) {
        // ---- load A tile [128 x 8], store transposed As[k][m]
        {
            const float4 v = *reinterpret_cast<const float4*>(
                &A[(size_t)(m0 + a_row) * lda + k0 + a_k4]);
            As[a_k4 + 0][a_row] = v.x;
            As[a_k4 + 1][a_row] = v.y;
            As[a_k4 + 2][a_row] = v.z;
            As[a_k4 + 3][a_row] = v.w;
        }
        // ---- load B tile
        if (TRANSB) {
            // B is [N,K]: same pattern as A
            const float4 v = *reinterpret_cast<const float4*>(
                &Bm[(size_t)(n0 + a_row) * ldb + k0 + a_k4]);
            Bs[a_k4 + 0][a_row] = v.x;
            Bs[a_k4 + 1][a_row] = v.y;
            Bs[a_k4 + 2][a_row] = v.z;
            Bs[a_k4 + 3][a_row] = v.w;
        } else {
            // B is [K,N]: k = tid/32 (0..7), n chunk = (tid%32)*4
            const int b_k  = tid >> 5;
            const int b_n4 = (tid & 31) * 4;
            const float4 v = *reinterpret_cast<const float4*>(
                &Bm[(size_t)(k0 + b_k) * ldb + n0 + b_n4]);
            *reinterpret_cast<float4*>(&Bs[b_k][b_n4]) = v;
        }
        __syncthreads();

#pragma unroll
        for (int kk = 0; kk < 8; kk++) {
            float4 a0 = *reinterpret_cast<const float4*>(&As[kk][ty * 8]);
            float4 a1 = *reinterpret_cast<const float4*>(&As[kk][ty * 8 + 4]);
            float4 b0 = *reinterpret_cast<const float4*>(&Bs[kk][tx * 8]);
            float4 b1 = *reinterpret_cast<const float4*>(&Bs[kk][tx * 8 + 4]);
            float a[8] = {a0.x, a0.y, a0.z, a0.w, a1.x, a1.y, a1.z, a1.w};
            float b[8] = {b0.x, b0.y, b0.z, b0.w, b1.x, b1.y, b1.z, b1.w};
#pragma unroll
            for (int i = 0; i < 8; i++)
#pragma unroll
                for (int j = 0; j < 8; j++)
                    acc[i][j] = fmaf(a[i], b[j], acc[i][j]);
        }
        __syncthreads();
    }

    // ---- epilogue
    const int row0 = m0 + ty * 8;
    const int col0 = n0 + tx * 8;
#pragma unroll
    for (int i = 0; i < 8; i++) {
        float* crow = &C[(size_t)(row0 + i) * ldc + col0];
#pragma unroll
        for (int j = 0; j < 8; j++) {
            float v = alpha * acc[i][j];
            if (bias != nullptr) v += __ldg(&bias[col0 + j]);
            crow[j] = v;
        }
    }
}

// ---------------------------------------------------------------------------
// Row softmax over attn rows of length SS=2048. One block (256 thr) per row.
// ---------------------------------------------------------------------------
__global__ __launch_bounds__(256) void softmax_kernel(float* __restrict__ attn)
{
    float* row = attn + (size_t)blockIdx.x * SS;
    __shared__ float red[256];
    const int t = threadIdx.x;

    float vals[8];
    float vmax = -INFINITY;
#pragma unroll
    for (int i = 0; i < 8; i++) {
        vals[i] = row[t + i * 256];
        vmax = fmaxf(vmax, vals[i]);
    }
    red[t] = vmax;
    __syncthreads();
#pragma unroll
    for (int s = 128; s > 0; s >>= 1) {
        if (t < s) red[t] = fmaxf(red[t], red[t + s]);
        __syncthreads();
    }
    vmax = red[0];
    __syncthreads();

    float sum = 0.0f;
#pragma unroll
    for (int i = 0; i < 8; i++) {
        vals[i] = expf(vals[i] - vmax);
        sum += vals[i];
    }
    red[t] = sum;
    __syncthreads();
#pragma unroll
    for (int s = 128; s > 0; s >>= 1) {
        if (t < s) red[t] += red[t + s];
        __syncthreads();
    }
    const float inv = 1.0f / red[0];
#pragma unroll
    for (int i = 0; i < 8; i++)
        row[t + i * 256] = vals[i] * inv;
}

extern "C" void kernel_launch(void* const* d_in, const int* in_sizes, int n_in,
                              void* d_out, int out_size)
{
    const float* X    = (const float*)d_in[0];  // [B,S,E]
    const float* W    = (const float*)d_in[1];  // [3E,E]
    const float* bias = (const float*)d_in[2];  // [3E]

    float* out  = (float*)d_out;                         // [B,S,E]
    float* attn = out + (size_t)BB * SS * EE;            // [B,S,S]

    float* qkv = nullptr;
    cudaGetSymbolAddress((void**)&qkv, g_qkv);

    // 1) qkv = X @ W^T + bias   : [8192,1024]@[3072,1024]^T -> [8192,3072]
    sgemm_kernel<true><<<dim3(FF / 128, (BB * SS) / 128, 1), 256>>>(
        X, W, qkv,
        BB * SS, FF, EE, EE, EE, FF,
        (size_t)0, (size_t)0, (size_t)0,
        bias, 1.0f);

    // 2) scores = Q @ K^T / sqrt(E)  per batch : [2048,1024]@[2048,1024]^T
    sgemm_kernel<true><<<dim3(SS / 128, SS / 128, BB), 256>>>(
        qkv, qkv + EE, attn,
        SS, SS, EE, FF, FF, SS,
        (size_t)SS * FF, (size_t)SS * FF, (size_t)SS * SS,
        nullptr, 1.0f / 32.0f);

    // 3) softmax rows (in place, in d_out's attention slice)
    softmax_kernel<<<BB * SS, 256>>>(attn);

    // 4) out = attn @ V  per batch : [2048,2048]@[2048,1024]
    sgemm_kernel<false><<<dim3(EE / 128, SS / 128, BB), 256>>>(
        attn, qkv + 2 * EE, out,
        SS, EE, SS, SS, FF, EE,
        (size_t)SS * SS, (size_t)SS * FF, (size_t)SS * EE,
        nullptr, 1.0f);
}

// round 6
// speedup vs baseline: 3.8518x; 3.8518x over previous
#include <cuda_runtime.h>
#include <cuda_bf16.h>
#include <math.h>
#include <stdint.h>

#define BB 4
#define SS 2048
#define EE 1024
#define FF 3072   // 3*EE

// ---------------- scratch (split-bf16 representations) ----------------
__device__ __nv_bfloat16 g_Xhi[(size_t)BB * SS * EE];
__device__ __nv_bfloat16 g_Xlo[(size_t)BB * SS * EE];
__device__ __nv_bfloat16 g_Whi[(size_t)FF * EE];
__device__ __nv_bfloat16 g_Wlo[(size_t)FF * EE];
__device__ __nv_bfloat16 g_qkv_hi[(size_t)BB * SS * FF];
__device__ __nv_bfloat16 g_qkv_lo[(size_t)BB * SS * FF];
__device__ __nv_bfloat16 g_attn_hi[(size_t)BB * SS * SS];
__device__ __nv_bfloat16 g_attn_lo[(size_t)BB * SS * SS];
__device__ __nv_bfloat16 g_vt_hi[(size_t)BB * EE * SS];
__device__ __nv_bfloat16 g_vt_lo[(size_t)BB * EE * SS];

// ---------------- PTX helpers ----------------
__device__ __forceinline__ uint32_t smem_u32(const void* p) {
    return (uint32_t)__cvta_generic_to_shared(p);
}
__device__ __forceinline__ void cp16(uint32_t s, const void* g) {
    asm volatile("cp.async.cg.shared.global [%0], [%1], 16;\n" :: "r"(s), "l"(g));
}
__device__ __forceinline__ void cp_commit() {
    asm volatile("cp.async.commit_group;\n" ::: "memory");
}
__device__ __forceinline__ void cp_wait0() {
    asm volatile("cp.async.wait_group 0;\n" ::: "memory");
}
__device__ __forceinline__ void ldsm4(uint32_t* r, uint32_t a) {
    asm volatile("ldmatrix.sync.aligned.m8n8.x4.shared.b16 {%0,%1,%2,%3}, [%4];"
        : "=r"(r[0]), "=r"(r[1]), "=r"(r[2]), "=r"(r[3]) : "r"(a));
}
__device__ __forceinline__ void ldsm2(uint32_t* r, uint32_t a) {
    asm volatile("ldmatrix.sync.aligned.m8n8.x2.shared.b16 {%0,%1}, [%2];"
        : "=r"(r[0]), "=r"(r[1]) : "r"(a));
}
__device__ __forceinline__ void mma_bf16(float* c, const uint32_t* a, const uint32_t* b) {
    asm volatile("mma.sync.aligned.m16n8k16.row.col.f32.bf16.bf16.f32 "
        "{%0,%1,%2,%3}, {%4,%5,%6,%7}, {%8,%9}, {%0,%1,%2,%3};"
        : "+f"(c[0]), "+f"(c[1]), "+f"(c[2]), "+f"(c[3])
        : "r"(a[0]), "r"(a[1]), "r"(a[2]), "r"(a[3]), "r"(b[0]), "r"(b[1]));
}

// ---------------- smem tile layout ----------------
// Per buffer: Ahi[128][40]bf16, Alo, Bhi[128][40], Blo. Row = 80B (5x16B chunks
// -> (r*5+c) mod 8 walks all banks: conflict-free ldmatrix/stores).
#define ROWB   80
#define A_LO   10240
#define B_HI   20480
#define B_LO   30720
#define BUFSZ  40960   // bytes per stage; 2 stages = 81920

__device__ __forceinline__ void load_tile(
    uint32_t sbase,
    const __nv_bfloat16* gAhi, const __nv_bfloat16* gAlo,
    const __nv_bfloat16* gBhi, const __nv_bfloat16* gBlo,
    int m0, int n0, int k0, int lda, int ldb, int tid)
{
#pragma unroll
    for (int i = 0; i < 2; i++) {
        int c = tid + i * 256;         // 0..511
        int row = c >> 2, cc = c & 3;  // 128 rows x 4 16B-chunks
        uint32_t so = row * ROWB + cc * 16;
        size_t ga = (size_t)(m0 + row) * lda + k0 + cc * 8;
        size_t gb = (size_t)(n0 + row) * ldb + k0 + cc * 8;
        cp16(sbase + so,        gAhi + ga);
        cp16(sbase + A_LO + so, gAlo + ga);
        cp16(sbase + B_HI + so, gBhi + gb);
        cp16(sbase + B_LO + so, gBlo + gb);
    }
}

// ---------------------------------------------------------------------------
// Split-bf16 GEMM:  C = alpha * (A @ B^T)   [3-term: AhBh + AhBl + AlBh]
// A: [M,K] row-major (hi/lo), B: [N,K] row-major (hi/lo).
// mode 0: C -> split bf16 (Chi/Clo) with bias added (fp32) first.
// mode 1: C -> fp32 Cf, scaled by alpha.
// blockIdx.z batches via element strides sA/sB/sC.
// ---------------------------------------------------------------------------
__global__ __launch_bounds__(256) void gemm_split(
    const __nv_bfloat16* __restrict__ Ahi, const __nv_bfloat16* __restrict__ Alo,
    const __nv_bfloat16* __restrict__ Bhi, const __nv_bfloat16* __restrict__ Blo,
    int K, int lda, int ldb, int ldc,
    size_t sA, size_t sB, size_t sC,
    int mode, float alpha,
    float* __restrict__ Cf,
    __nv_bfloat16* __restrict__ Chi, __nv_bfloat16* __restrict__ Clo,
    const float* __restrict__ bias)
{
    extern __shared__ char dynsmem[];
    const int tid  = threadIdx.x;
    const int lane = tid & 31;
    const int wid  = tid >> 5;
    const int wm   = wid & 1;   // 2 warp rows (64 each)
    const int wn   = wid >> 1;  // 4 warp cols (32 each)

    const int m0 = blockIdx.y * 128;
    const int n0 = blockIdx.x * 128;
    const int z  = blockIdx.z;

    Ahi += sA * z; Alo += sA * z;
    Bhi += sB * z; Blo += sB * z;

    // ldmatrix per-lane address components
    const int a_row = ((lane >> 3) & 1) * 8 + (lane & 7);
    const int a_k16 = ((lane >> 4) & 1) * 16;          // bytes
    const int b_row = lane & 7;
    const int b_k16 = ((lane >> 3) & 1) * 16;          // bytes

    float acc[4][4][4];
#pragma unroll
    for (int mt = 0; mt < 4; mt++)
#pragma unroll
        for (int nt = 0; nt < 4; nt++)
#pragma unroll
            for (int k = 0; k < 4; k++) acc[mt][nt][k] = 0.0f;

    const uint32_t sb = smem_u32(dynsmem);
    const int KT = K >> 5;

    load_tile(sb, Ahi, Alo, Bhi, Blo, m0, n0, 0, lda, ldb, tid);
    cp_commit();

    int cur = 0;
    for (int kt = 0; kt < KT; kt++) {
        cp_wait0();
        __syncthreads();
        if (kt + 1 < KT) {
            load_tile(sb + (cur ^ 1) * BUFSZ, Ahi, Alo, Bhi, Blo,
                      m0, n0, (kt + 1) * 32, lda, ldb, tid);
            cp_commit();
        }
        const uint32_t base = sb + cur * BUFSZ;
#pragma unroll
        for (int ks = 0; ks < 2; ks++) {
            uint32_t bh[4][2], bl[4][2];
#pragma unroll
            for (int nt = 0; nt < 4; nt++) {
                uint32_t ad = base + B_HI +
                    (uint32_t)(wn * 32 + nt * 8 + b_row) * ROWB + ks * 32 + b_k16;
                ldsm2(bh[nt], ad);
                ldsm2(bl[nt], ad + 10240);
            }
#pragma unroll
            for (int mt = 0; mt < 4; mt++) {
                uint32_t ah[4], al[4];
                uint32_t ad = base +
                    (uint32_t)(wm * 64 + mt * 16 + a_row) * ROWB + ks * 32 + a_k16;
                ldsm4(ah, ad);
                ldsm4(al, ad + A_LO);
#pragma unroll
                for (int nt = 0; nt < 4; nt++) {
                    mma_bf16(acc[mt][nt], ah, bh[nt]);
                    mma_bf16(acc[mt][nt], ah, bl[nt]);
                    mma_bf16(acc[mt][nt], al, bh[nt]);
                }
            }
        }
        cur ^= 1;
    }

    // ---- epilogue
    const int g = lane >> 2, q = lane & 3;
    const int rbase = m0 + wm * 64;
    const int cbase = n0 + wn * 32;

    if (mode == 1) {
        Cf += sC * z;
#pragma unroll
        for (int mt = 0; mt < 4; mt++) {
#pragma unroll
            for (int nt = 0; nt < 4; nt++) {
                int r = rbase + mt * 16 + g;
                int c = cbase + nt * 8 + q * 2;
                float2 v0 = make_float2(alpha * acc[mt][nt][0], alpha * acc[mt][nt][1]);
                float2 v1 = make_float2(alpha * acc[mt][nt][2], alpha * acc[mt][nt][3]);
                *reinterpret_cast<float2*>(&Cf[(size_t)r * ldc + c]) = v0;
                *reinterpret_cast<float2*>(&Cf[(size_t)(r + 8) * ldc + c]) = v1;
            }
        }
    } else {
        Chi += sC * z; Clo += sC * z;
#pragma unroll
        for (int mt = 0; mt < 4; mt++) {
#pragma unroll
            for (int nt = 0; nt < 4; nt++) {
                int r = rbase + mt * 16 + g;
                int c = cbase + nt * 8 + q * 2;
                float b0 = bias[c], b1 = bias[c + 1];
#pragma unroll
                for (int hh = 0; hh < 2; hh++) {
                    float v0 = acc[mt][nt][hh * 2 + 0] + b0;
                    float v1 = acc[mt][nt][hh * 2 + 1] + b1;
                    __nv_bfloat16 h0 = __float2bfloat16(v0);
                    __nv_bfloat16 h1 = __float2bfloat16(v1);
                    __nv_bfloat16 l0 = __float2bfloat16(v0 - __bfloat162float(h0));
                    __nv_bfloat16 l1 = __float2bfloat16(v1 - __bfloat162float(h1));
                    size_t off = (size_t)(r + hh * 8) * ldc + c;
                    *reinterpret_cast<__nv_bfloat162*>(&Chi[off]) = __halves2bfloat162(h0, h1);
                    *reinterpret_cast<__nv_bfloat162*>(&Clo[off]) = __halves2bfloat162(l0, l1);
                }
            }
        }
    }
}

// ---------------------------------------------------------------------------
// fp32 -> split bf16 (hi + lo), 4 elems/thread
// ---------------------------------------------------------------------------
__global__ __launch_bounds__(256) void split_fp32(
    const float4* __restrict__ x, __nv_bfloat16* __restrict__ hi,
    __nv_bfloat16* __restrict__ lo, size_t n4)
{
    size_t i = (size_t)blockIdx.x * 256 + threadIdx.x;
    if (i >= n4) return;
    float4 v = x[i];
    float vv[4] = {v.x, v.y, v.z, v.w};
    __nv_bfloat16 h[4], l[4];
#pragma unroll
    for (int j = 0; j < 4; j++) {
        h[j] = __float2bfloat16(vv[j]);
        l[j] = __float2bfloat16(vv[j] - __bfloat162float(h[j]));
    }
    *reinterpret_cast<__nv_bfloat162*>(&hi[i * 4])     = __halves2bfloat162(h[0], h[1]);
    *reinterpret_cast<__nv_bfloat162*>(&hi[i * 4 + 2]) = __halves2bfloat162(h[2], h[3]);
    *reinterpret_cast<__nv_bfloat162*>(&lo[i * 4])     = __halves2bfloat162(l[0], l[1]);
    *reinterpret_cast<__nv_bfloat162*>(&lo[i * 4 + 2]) = __halves2bfloat162(l[2], l[3]);
}

// ---------------------------------------------------------------------------
// Transpose V slice of qkv (cols [2048,3072)) -> Vt[b][e][s], hi & lo
// ---------------------------------------------------------------------------
__global__ __launch_bounds__(256) void transposeV(
    const __nv_bfloat16* __restrict__ qhi, const __nv_bfloat16* __restrict__ qlo,
    __nv_bfloat16* __restrict__ vthi, __nv_bfloat16* __restrict__ vtlo)
{
    __shared__ __nv_bfloat16 th[32][33], tl[32][33];
    int b  = blockIdx.z;
    int s0 = blockIdx.x * 32;
    int e0 = blockIdx.y * 32;
    int tx = threadIdx.x, ty = threadIdx.y;   // 32 x 8
#pragma unroll
    for (int j = 0; j < 4; j++) {
        int s = s0 + ty + j * 8;
        size_t gi = (size_t)(b * SS + s) * FF + 2 * EE + e0 + tx;
        th[ty + j * 8][tx] = qhi[gi];
        tl[ty + j * 8][tx] = qlo[gi];
    }
    __syncthreads();
#pragma unroll
    for (int j = 0; j < 4; j++) {
        int e = e0 + ty + j * 8;
        size_t go = (size_t)b * EE * SS + (size_t)e * SS + s0 + tx;
        vthi[go] = th[tx][ty + j * 8];
        vtlo[go] = tl[tx][ty + j * 8];
    }
}

// ---------------------------------------------------------------------------
// Row softmax (fp32 in place) + write split-bf16 copy for the AV GEMM
// ---------------------------------------------------------------------------
__global__ __launch_bounds__(256) void softmax_split(
    float* __restrict__ attn,
    __nv_bfloat16* __restrict__ ahi, __nv_bfloat16* __restrict__ alo)
{
    size_t rbase = (size_t)blockIdx.x * SS;
    float* row = attn + rbase;
    __shared__ float red[256];
    const int t = threadIdx.x;

    float vals[8];
    float vmax = -INFINITY;
#pragma unroll
    for (int i = 0; i < 8; i++) {
        vals[i] = row[t + i * 256];
        vmax = fmaxf(vmax, vals[i]);
    }
    red[t] = vmax;
    __syncthreads();
#pragma unroll
    for (int s = 128; s > 0; s >>= 1) {
        if (t < s) red[t] = fmaxf(red[t], red[t + s]);
        __syncthreads();
    }
    vmax = red[0];
    __syncthreads();

    float sum = 0.0f;
#pragma unroll
    for (int i = 0; i < 8; i++) {
        vals[i] = __expf(vals[i] - vmax);
        sum += vals[i];
    }
    red[t] = sum;
    __syncthreads();
#pragma unroll
    for (int s = 128; s > 0; s >>= 1) {
        if (t < s) red[t] += red[t + s];
        __syncthreads();
    }
    const float inv = 1.0f / red[0];
#pragma unroll
    for (int i = 0; i < 8; i++) {
        float v = vals[i] * inv;
        int idx = t + i * 256;
        row[idx] = v;
        __nv_bfloat16 h = __float2bfloat16(v);
        ahi[rbase + idx] = h;
        alo[rbase + idx] = __float2bfloat16(v - __bfloat162float(h));
    }
}

// ---------------------------------------------------------------------------
extern "C" void kernel_launch(void* const* d_in, const int* in_sizes, int n_in,
                              void* d_out, int out_size)
{
    const float* X    = (const float*)d_in[0];  // [B,S,E]
    const float* W    = (const float*)d_in[1];  // [3E,E]
    const float* bias = (const float*)d_in[2];  // [3E]

    float* out  = (float*)d_out;                 // [B,S,E]
    float* attn = out + (size_t)BB * SS * EE;    // [B,S,S]

    __nv_bfloat16 *Xhi, *Xlo, *Whi, *Wlo, *Qhi, *Qlo, *Ahi, *Alo, *Vthi, *Vtlo;
    cudaGetSymbolAddress((void**)&Xhi, g_Xhi);
    cudaGetSymbolAddress((void**)&Xlo, g_Xlo);
    cudaGetSymbolAddress((void**)&Whi, g_Whi);
    cudaGetSymbolAddress((void**)&Wlo, g_Wlo);
    cudaGetSymbolAddress((void**)&Qhi, g_qkv_hi);
    cudaGetSymbolAddress((void**)&Qlo, g_qkv_lo);
    cudaGetSymbolAddress((void**)&Ahi, g_attn_hi);
    cudaGetSymbolAddress((void**)&Alo, g_attn_lo);
    cudaGetSymbolAddress((void**)&Vthi, g_vt_hi);
    cudaGetSymbolAddress((void**)&Vtlo, g_vt_lo);

    (void)cudaFuncSetAttribute(gemm_split,
        cudaFuncAttributeMaxDynamicSharedMemorySize, 2 * BUFSZ);

    // 1) split inputs
    split_fp32<<<(BB * SS * EE / 4 + 255) / 256, 256>>>(
        (const float4*)X, Xhi, Xlo, (size_t)BB * SS * EE / 4);
    split_fp32<<<(FF * EE / 4 + 255) / 256, 256>>>(
        (const float4*)W, Whi, Wlo, (size_t)FF * EE / 4);

    // 2) qkv = X @ W^T + bias  -> split bf16   [8192,3072]
    gemm_split<<<dim3(FF / 128, (BB * SS) / 128, 1), 256, 2 * BUFSZ>>>(
        Xhi, Xlo, Whi, Wlo,
        EE, EE, EE, FF,
        (size_t)0, (size_t)0, (size_t)0,
        0, 1.0f, nullptr, Qhi, Qlo, bias);

    // 3) V^T for the AV GEMM
    transposeV<<<dim3(SS / 32, EE / 32, BB), dim3(32, 8)>>>(Qhi, Qlo, Vthi, Vtlo);

    // 4) scores = Q @ K^T / 32 -> fp32 attn slice
    gemm_split<<<dim3(SS / 128, SS / 128, BB), 256, 2 * BUFSZ>>>(
        Qhi, Qlo, Qhi + EE, Qlo + EE,
        EE, FF, FF, SS,
        (size_t)SS * FF, (size_t)SS * FF, (size_t)SS * SS,
        1, 1.0f / 32.0f, attn, nullptr, nullptr, nullptr);

    // 5) softmax rows (fp32 in place) + split copy
    softmax_split<<<BB * SS, 256>>>(attn, Ahi, Alo);

    // 6) out = attn @ Vt^T  -> fp32  [2048,1024] per batch
    gemm_split<<<dim3(EE / 128, SS / 128, BB), 256, 2 * BUFSZ>>>(
        Ahi, Alo, Vthi, Vtlo,
        SS, SS, SS, EE,
        (size_t)SS * SS, (size_t)EE * SS, (size_t)SS * EE,
        1, 1.0f, out, nullptr, nullptr, nullptr);
}

// round 8
// speedup vs baseline: 3.9042x; 1.0136x over previous
#include <cuda_runtime.h>
#include <cuda_bf16.h>
#include <math.h>
#include <stdint.h>

#define BB 4
#define SS 2048
#define EE 1024
#define FF 3072   // 3*EE

// ---------------- scratch (split-bf16 representations) ----------------
__device__ __nv_bfloat16 g_Xhi[(size_t)BB * SS * EE];
__device__ __nv_bfloat16 g_Xlo[(size_t)BB * SS * EE];
__device__ __nv_bfloat16 g_Whi[(size_t)FF * EE];
__device__ __nv_bfloat16 g_Wlo[(size_t)FF * EE];
__device__ __nv_bfloat16 g_qkv_hi[(size_t)BB * SS * FF];
__device__ __nv_bfloat16 g_qkv_lo[(size_t)BB * SS * FF];
__device__ __nv_bfloat16 g_attn_hi[(size_t)BB * SS * SS];
__device__ __nv_bfloat16 g_attn_lo[(size_t)BB * SS * SS];
__device__ __nv_bfloat16 g_vt_hi[(size_t)BB * EE * SS];
__device__ __nv_bfloat16 g_vt_lo[(size_t)BB * EE * SS];

// ---------------- PTX helpers ----------------
__device__ __forceinline__ uint32_t smem_u32(const void* p) {
    return (uint32_t)__cvta_generic_to_shared(p);
}
__device__ __forceinline__ void cp16(uint32_t s, const void* g) {
    asm volatile("cp.async.cg.shared.global [%0], [%1], 16;\n" :: "r"(s), "l"(g));
}
__device__ __forceinline__ void cp_commit() {
    asm volatile("cp.async.commit_group;\n" ::: "memory");
}
__device__ __forceinline__ void cp_wait1() {
    asm volatile("cp.async.wait_group 1;\n" ::: "memory");
}
__device__ __forceinline__ void ldsm4(uint32_t* r, uint32_t a) {
    asm volatile("ldmatrix.sync.aligned.m8n8.x4.shared.b16 {%0,%1,%2,%3}, [%4];"
        : "=r"(r[0]), "=r"(r[1]), "=r"(r[2]), "=r"(r[3]) : "r"(a));
}
__device__ __forceinline__ void mma_bf16(float* c, const uint32_t* a, const uint32_t* b) {
    asm volatile("mma.sync.aligned.m16n8k16.row.col.f32.bf16.bf16.f32 "
        "{%0,%1,%2,%3}, {%4,%5,%6,%7}, {%8,%9}, {%0,%1,%2,%3};"
        : "+f"(c[0]), "+f"(c[1]), "+f"(c[2]), "+f"(c[3])
        : "r"(a[0]), "r"(a[1]), "r"(a[2]), "r"(a[3]), "r"(b[0]), "r"(b[1]));
}

// ---------------- smem tile layout ----------------
// Per stage: Ahi[128][40]bf16, Alo, Bhi[128][40], Blo. Row = 80B (5x16B chunks
// -> (r*5+c) mod 8 walks all banks: conflict-free ldmatrix/stores).
#define ROWB   80
#define A_LO   10240
#define B_HI   20480
#define B_LO   30720
#define STAGE_B 40960
#define NSTAGE 3
#define SMEM_DYN (NSTAGE * STAGE_B)   // 122880

__device__ __forceinline__ void load_stage(
    uint32_t sbase,
    const __nv_bfloat16* gAhi, const __nv_bfloat16* gAlo,
    const __nv_bfloat16* gBhi, const __nv_bfloat16* gBlo,
    int m0, int n0, int k0, int lda, int ldb, int tid)
{
#pragma unroll
    for (int i = 0; i < 2; i++) {
        int c = tid + i * 256;         // 0..511
        int row = c >> 2, cc = c & 3;  // 128 rows x 4 16B-chunks
        uint32_t so = row * ROWB + cc * 16;
        size_t ga = (size_t)(m0 + row) * lda + k0 + cc * 8;
        size_t gb = (size_t)(n0 + row) * ldb + k0 + cc * 8;
        cp16(sbase + so,        gAhi + ga);
        cp16(sbase + A_LO + so, gAlo + ga);
        cp16(sbase + B_HI + so, gBhi + gb);
        cp16(sbase + B_LO + so, gBlo + gb);
    }
}

// ---------------------------------------------------------------------------
// Split-bf16 GEMM:  C = alpha * (A @ B^T)   [3-term: AhBh + AhBl + AlBh]
// A: [M,K] row-major (hi/lo), B: [N,K] row-major (hi/lo).
// mode 0: C -> split bf16 (Chi/Clo) with bias added (fp32) first.
// mode 1: C -> fp32 Cf, scaled by alpha.
// 3-stage cp.async pipeline, prefetch distance 2 (wait_group 1).
// ---------------------------------------------------------------------------
__global__ __launch_bounds__(256, 1) void gemm_split(
    const __nv_bfloat16* __restrict__ Ahi, const __nv_bfloat16* __restrict__ Alo,
    const __nv_bfloat16* __restrict__ Bhi, const __nv_bfloat16* __restrict__ Blo,
    int K, int lda, int ldb, int ldc,
    size_t sA, size_t sB, size_t sC,
    int mode, float alpha,
    float* __restrict__ Cf,
    __nv_bfloat16* __restrict__ Chi, __nv_bfloat16* __restrict__ Clo,
    const float* __restrict__ bias)
{
    extern __shared__ char dynsmem[];
    const int tid  = threadIdx.x;
    const int lane = tid & 31;
    const int wid  = tid >> 5;
    const int wm   = wid & 1;   // 2 warp rows (64 each)
    const int wn   = wid >> 1;  // 4 warp cols (32 each)

    const int m0 = blockIdx.y * 128;
    const int n0 = blockIdx.x * 128;
    const int z  = blockIdx.z;

    Ahi += sA * z; Alo += sA * z;
    Bhi += sB * z; Blo += sB * z;

    // ldmatrix per-lane address components
    const int a_row = ((lane >> 3) & 1) * 8 + (lane & 7);
    const int a_k16 = ((lane >> 4) & 1) * 16;          // bytes
    // fused B x4: lanes 0-15 -> hi (2 matrices), lanes 16-31 -> lo (2 matrices)
    const int b_row = lane & 7;
    const int b_k16 = ((lane >> 3) & 1) * 16;          // bytes
    const int b_hl  = ((lane >> 4) & 1) * (B_LO - B_HI);

    float acc[4][4][4];
#pragma unroll
    for (int mt = 0; mt < 4; mt++)
#pragma unroll
        for (int nt = 0; nt < 4; nt++)
#pragma unroll
            for (int k = 0; k < 4; k++) acc[mt][nt][k] = 0.0f;

    const uint32_t sb = smem_u32(dynsmem);
    const int KT = K >> 5;

    // prologue: stages 0,1
    load_stage(sb,           Ahi, Alo, Bhi, Blo, m0, n0, 0,  lda, ldb, tid);
    cp_commit();
    load_stage(sb + STAGE_B, Ahi, Alo, Bhi, Blo, m0, n0, 32, lda, ldb, tid);
    cp_commit();

    int s_cur = 0, s_pf = 2;
    for (int kt = 0; kt < KT; kt++) {
        cp_wait1();              // load(kt) complete; load(kt+1) may be in flight
        __syncthreads();

        if (kt + 2 < KT) {
            load_stage(sb + s_pf * STAGE_B, Ahi, Alo, Bhi, Blo,
                       m0, n0, (kt + 2) * 32, lda, ldb, tid);
        }
        cp_commit();             // uniform: keeps group accounting exact

        const uint32_t base = sb + s_cur * STAGE_B;
#pragma unroll
        for (int ks = 0; ks < 2; ks++) {
            // fused hi/lo B fragments: one ldsm4 per nt
            uint32_t bf[4][4];
#pragma unroll
            for (int nt = 0; nt < 4; nt++) {
                uint32_t ad = base + B_HI + b_hl +
                    (uint32_t)(wn * 32 + nt * 8 + b_row) * ROWB + ks * 32 + b_k16;
                ldsm4(bf[nt], ad);
            }
#pragma unroll
            for (int mt = 0; mt < 4; mt++) {
                uint32_t ah[4], al[4];
                uint32_t ad = base +
                    (uint32_t)(wm * 64 + mt * 16 + a_row) * ROWB + ks * 32 + a_k16;
                ldsm4(ah, ad);
                ldsm4(al, ad + A_LO);
#pragma unroll
                for (int nt = 0; nt < 4; nt++) {
                    mma_bf16(acc[mt][nt], ah, &bf[nt][0]);   // Ah*Bh
                    mma_bf16(acc[mt][nt], ah, &bf[nt][2]);   // Ah*Bl
                    mma_bf16(acc[mt][nt], al, &bf[nt][0]);   // Al*Bh
                }
            }
        }
        s_cur = (s_cur + 1 == NSTAGE) ? 0 : s_cur + 1;
        s_pf  = (s_pf  + 1 == NSTAGE) ? 0 : s_pf  + 1;
    }

    // ---- epilogue
    const int g = lane >> 2, q = lane & 3;
    const int rbase = m0 + wm * 64;
    const int cbase = n0 + wn * 32;

    if (mode == 1) {
        Cf += sC * z;
#pragma unroll
        for (int mt = 0; mt < 4; mt++) {
#pragma unroll
            for (int nt = 0; nt < 4; nt++) {
                int r = rbase + mt * 16 + g;
                int c = cbase + nt * 8 + q * 2;
                float2 v0 = make_float2(alpha * acc[mt][nt][0], alpha * acc[mt][nt][1]);
                float2 v1 = make_float2(alpha * acc[mt][nt][2], alpha * acc[mt][nt][3]);
                *reinterpret_cast<float2*>(&Cf[(size_t)r * ldc + c]) = v0;
                *reinterpret_cast<float2*>(&Cf[(size_t)(r + 8) * ldc + c]) = v1;
            }
        }
    } else {
        Chi += sC * z; Clo += sC * z;
#pragma unroll
        for (int mt = 0; mt < 4; mt++) {
#pragma unroll
            for (int nt = 0; nt < 4; nt++) {
                int r = rbase + mt * 16 + g;
                int c = cbase + nt * 8 + q * 2;
                float b0 = bias[c], b1 = bias[c + 1];
#pragma unroll
                for (int hh = 0; hh < 2; hh++) {
                    float v0 = acc[mt][nt][hh * 2 + 0] + b0;
                    float v1 = acc[mt][nt][hh * 2 + 1] + b1;
                    __nv_bfloat16 h0 = __float2bfloat16(v0);
                    __nv_bfloat16 h1 = __float2bfloat16(v1);
                    __nv_bfloat16 l0 = __float2bfloat16(v0 - __bfloat162float(h0));
                    __nv_bfloat16 l1 = __float2bfloat16(v1 - __bfloat162float(h1));
                    size_t off = (size_t)(r + hh * 8) * ldc + c;
                    *reinterpret_cast<__nv_bfloat162*>(&Chi[off]) = __halves2bfloat162(h0, h1);
                    *reinterpret_cast<__nv_bfloat162*>(&Clo[off]) = __halves2bfloat162(l0, l1);
                }
            }
        }
    }
}

// ---------------------------------------------------------------------------
// fp32 -> split bf16 (hi + lo), 4 elems/thread
// ---------------------------------------------------------------------------
__global__ __launch_bounds__(256) void split_fp32(
    const float4* __restrict__ x, __nv_bfloat16* __restrict__ hi,
    __nv_bfloat16* __restrict__ lo, size_t n4)
{
    size_t i = (size_t)blockIdx.x * 256 + threadIdx.x;
    if (i >= n4) return;
    float4 v = x[i];
    float vv[4] = {v.x, v.y, v.z, v.w};
    __nv_bfloat16 h[4], l[4];
#pragma unroll
    for (int j = 0; j < 4; j++) {
        h[j] = __float2bfloat16(vv[j]);
        l[j] = __float2bfloat16(vv[j] - __bfloat162float(h[j]));
    }
    *reinterpret_cast<__nv_bfloat162*>(&hi[i * 4])     = __halves2bfloat162(h[0], h[1]);
    *reinterpret_cast<__nv_bfloat162*>(&hi[i * 4 + 2]) = __halves2bfloat162(h[2], h[3]);
    *reinterpret_cast<__nv_bfloat162*>(&lo[i * 4])     = __halves2bfloat162(l[0], l[1]);
    *reinterpret_cast<__nv_bfloat162*>(&lo[i * 4 + 2]) = __halves2bfloat162(l[2], l[3]);
}

// ---------------------------------------------------------------------------
// Transpose V slice of qkv (cols [2048,3072)) -> Vt[b][e][s], hi & lo
// ---------------------------------------------------------------------------
__global__ __launch_bounds__(256) void transposeV(
    const __nv_bfloat16* __restrict__ qhi, const __nv_bfloat16* __restrict__ qlo,
    __nv_bfloat16* __restrict__ vthi, __nv_bfloat16* __restrict__ vtlo)
{
    __shared__ __nv_bfloat16 th[32][33], tl[32][33];
    int b  = blockIdx.z;
    int s0 = blockIdx.x * 32;
    int e0 = blockIdx.y * 32;
    int tx = threadIdx.x, ty = threadIdx.y;   // 32 x 8
#pragma unroll
    for (int j = 0; j < 4; j++) {
        int s = s0 + ty + j * 8;
        size_t gi = (size_t)(b * SS + s) * FF + 2 * EE + e0 + tx;
        th[ty + j * 8][tx] = qhi[gi];
        tl[ty + j * 8][tx] = qlo[gi];
    }
    __syncthreads();
#pragma unroll
    for (int j = 0; j < 4; j++) {
        int e = e0 + ty + j * 8;
        size_t go = (size_t)b * EE * SS + (size_t)e * SS + s0 + tx;
        vthi[go] = th[tx][ty + j * 8];
        vtlo[go] = tl[tx][ty + j * 8];
    }
}

// ---------------------------------------------------------------------------
// Row softmax (fp32 in place) + write split-bf16 copy for the AV GEMM
// ---------------------------------------------------------------------------
__global__ __launch_bounds__(256) void softmax_split(
    float* __restrict__ attn,
    __nv_bfloat16* __restrict__ ahi, __nv_bfloat16* __restrict__ alo)
{
    size_t rbase = (size_t)blockIdx.x * SS;
    float* row = attn + rbase;
    __shared__ float red[256];
    const int t = threadIdx.x;

    float vals[8];
    float vmax = -INFINITY;
#pragma unroll
    for (int i = 0; i < 8; i++) {
        vals[i] = row[t + i * 256];
        vmax = fmaxf(vmax, vals[i]);
    }
    red[t] = vmax;
    __syncthreads();
#pragma unroll
    for (int s = 128; s > 0; s >>= 1) {
        if (t < s) red[t] = fmaxf(red[t], red[t + s]);
        __syncthreads();
    }
    vmax = red[0];
    __syncthreads();

    float sum = 0.0f;
#pragma unroll
    for (int i = 0; i < 8; i++) {
        vals[i] = __expf(vals[i] - vmax);
        sum += vals[i];
    }
    red[t] = sum;
    __syncthreads();
#pragma unroll
    for (int s = 128; s > 0; s >>= 1) {
        if (t < s) red[t] += red[t + s];
        __syncthreads();
    }
    const float inv = 1.0f / red[0];
#pragma unroll
    for (int i = 0; i < 8; i++) {
        float v = vals[i] * inv;
        int idx = t + i * 256;
        row[idx] = v;
        __nv_bfloat16 h = __float2bfloat16(v);
        ahi[rbase + idx] = h;
        alo[rbase + idx] = __float2bfloat16(v - __bfloat162float(h));
    }
}

// ---------------------------------------------------------------------------
extern "C" void kernel_launch(void* const* d_in, const int* in_sizes, int n_in,
                              void* d_out, int out_size)
{
    const float* X    = (const float*)d_in[0];  // [B,S,E]
    const float* W    = (const float*)d_in[1];  // [3E,E]
    const float* bias = (const float*)d_in[2];  // [3E]

    float* out  = (float*)d_out;                 // [B,S,E]
    float* attn = out + (size_t)BB * SS * EE;    // [B,S,S]

    __nv_bfloat16 *Xhi, *Xlo, *Whi, *Wlo, *Qhi, *Qlo, *Ahi, *Alo, *Vthi, *Vtlo;
    cudaGetSymbolAddress((void**)&Xhi, g_Xhi);
    cudaGetSymbolAddress((void**)&Xlo, g_Xlo);
    cudaGetSymbolAddress((void**)&Whi, g_Whi);
    cudaGetSymbolAddress((void**)&Wlo, g_Wlo);
    cudaGetSymbolAddress((void**)&Qhi, g_qkv_hi);
    cudaGetSymbolAddress((void**)&Qlo, g_qkv_lo);
    cudaGetSymbolAddress((void**)&Ahi, g_attn_hi);
    cudaGetSymbolAddress((void**)&Alo, g_attn_lo);
    cudaGetSymbolAddress((void**)&Vthi, g_vt_hi);
    cudaGetSymbolAddress((void**)&Vtlo, g_vt_lo);

    (void)cudaFuncSetAttribute(gemm_split,
        cudaFuncAttributeMaxDynamicSharedMemorySize, SMEM_DYN);

    // 1) split inputs
    split_fp32<<<(BB * SS * EE / 4 + 255) / 256, 256>>>(
        (const float4*)X, Xhi, Xlo, (size_t)BB * SS * EE / 4);
    split_fp32<<<(FF * EE / 4 + 255) / 256, 256>>>(
        (const float4*)W, Whi, Wlo, (size_t)FF * EE / 4);

    // 2) qkv = X @ W^T + bias  -> split bf16   [8192,3072]
    gemm_split<<<dim3(FF / 128, (BB * SS) / 128, 1), 256, SMEM_DYN>>>(
        Xhi, Xlo, Whi, Wlo,
        EE, EE, EE, FF,
        (size_t)0, (size_t)0, (size_t)0,
        0, 1.0f, nullptr, Qhi, Qlo, bias);

    // 3) V^T for the AV GEMM
    transposeV<<<dim3(SS / 32, EE / 32, BB), dim3(32, 8)>>>(Qhi, Qlo, Vthi, Vtlo);

    // 4) scores = Q @ K^T / 32 -> fp32 attn slice
    gemm_split<<<dim3(SS / 128, SS / 128, BB), 256, SMEM_DYN>>>(
        Qhi, Qlo, Qhi + EE, Qlo + EE,
        EE, FF, FF, SS,
        (size_t)SS * FF, (size_t)SS * FF, (size_t)SS * SS,
        1, 1.0f / 32.0f, attn, nullptr, nullptr, nullptr);

    // 5) softmax rows (fp32 in place) + split copy
    softmax_split<<<BB * SS, 256>>>(attn, Ahi, Alo);

    // 6) out = attn @ Vt^T  -> fp32  [2048,1024] per batch
    gemm_split<<<dim3(EE / 128, SS / 128, BB), 256, SMEM_DYN>>>(
        Ahi, Alo, Vthi, Vtlo,
        SS, SS, SS, EE,
        (size_t)SS * SS, (size_t)EE * SS, (size_t)SS * EE,
        1, 1.0f, out, nullptr, nullptr, nullptr);
}

// round 9
// speedup vs baseline: 6.4699x; 1.6572x over previous
#include <cuda_runtime.h>
#include <cuda_fp16.h>
#include <math.h>
#include <stdint.h>

#define BB 4
#define SS 2048
#define EE 1024
#define FF 3072   // 3*EE

// ---------------- scratch (fp16 / split-fp16 representations) ----------------
__device__ __half g_Xh[(size_t)BB * SS * EE];
__device__ __half g_Wh[(size_t)FF * EE];
__device__ __half g_Wl[(size_t)FF * EE];
__device__ __half g_qkv_h[(size_t)BB * SS * FF];
__device__ __half g_qkv_l[(size_t)BB * SS * FF];
__device__ __half g_attn_h[(size_t)BB * SS * SS];
__device__ __half g_vt_h[(size_t)BB * EE * SS];
__device__ __half g_vt_l[(size_t)BB * EE * SS];

// ---------------- PTX helpers ----------------
__device__ __forceinline__ uint32_t smem_u32(const void* p) {
    return (uint32_t)__cvta_generic_to_shared(p);
}
__device__ __forceinline__ void cp16(uint32_t s, const void* g) {
    asm volatile("cp.async.cg.shared.global [%0], [%1], 16;\n" :: "r"(s), "l"(g));
}
__device__ __forceinline__ void cp_commit() {
    asm volatile("cp.async.commit_group;\n" ::: "memory");
}
__device__ __forceinline__ void cp_wait1() {
    asm volatile("cp.async.wait_group 1;\n" ::: "memory");
}
__device__ __forceinline__ void ldsm4(uint32_t* r, uint32_t a) {
    asm volatile("ldmatrix.sync.aligned.m8n8.x4.shared.b16 {%0,%1,%2,%3}, [%4];"
        : "=r"(r[0]), "=r"(r[1]), "=r"(r[2]), "=r"(r[3]) : "r"(a));
}
__device__ __forceinline__ void mma_f16(float* c, const uint32_t* a, const uint32_t* b) {
    asm volatile("mma.sync.aligned.m16n8k16.row.col.f32.f16.f16.f32 "
        "{%0,%1,%2,%3}, {%4,%5,%6,%7}, {%8,%9}, {%0,%1,%2,%3};"
        : "+f"(c[0]), "+f"(c[1]), "+f"(c[2]), "+f"(c[3])
        : "r"(a[0]), "r"(a[1]), "r"(a[2]), "r"(a[3]), "r"(b[0]), "r"(b[1]));
}

// ---------------- smem tile layout ----------------
// Per stage: Ah[128][40]fp16, Bh[128][40], Bl[128][40]. Row = 80B (5x16B chunks
// -> (r*5+c) mod 8 walks all banks: conflict-free ldmatrix/stores).
// Only chunks 0..3 (64B = BK=32 fp16) carry data; chunk 4 is pad.
#define ROWB    80
#define B_HI    10240
#define B_LO    20480
#define STAGE_B 30720
#define NSTAGE  3
#define SMEM_DYN (NSTAGE * STAGE_B)   // 92160

__device__ __forceinline__ void load_stage(
    uint32_t sbase,
    const __half* gAh, const __half* gBh, const __half* gBl,
    int m0, int n0, int k0, int lda, int ldb, int tid)
{
#pragma unroll
    for (int i = 0; i < 6; i++) {
        const int tile = i >> 1;               // 0:Ah 1:Bh 2:Bl
        int rem = tid + (i & 1) * 256;         // 0..511
        int row = rem >> 2, cc = rem & 3;      // 128 rows x 4 16B-chunks
        uint32_t so = sbase + tile * B_HI + row * ROWB + cc * 16;
        const __half* gp;
        if (tile == 0) gp = gAh + (size_t)(m0 + row) * lda + k0 + cc * 8;
        else {
            size_t go = (size_t)(n0 + row) * ldb + k0 + cc * 8;
            gp = (tile == 1 ? gBh : gBl) + go;
        }
        cp16(so, gp);
    }
}

// ---------------------------------------------------------------------------
// 2-term split-fp16 GEMM:  C = alpha * (A @ B^T) = Ah*Bh + Ah*Bl
// A: [M,K] fp16 (unsplit), B: [N,K] fp16 hi/lo. K-major, BK=32, 128x128 tiles.
// mode 0: C -> split fp16 (Ch/Cl) with fp32 bias added first.
// mode 1: C -> fp32 Cf, scaled by alpha.
// 3-stage cp.async pipeline, prefetch distance 2 (wait_group 1).
// ---------------------------------------------------------------------------
__global__ __launch_bounds__(256, 2) void gemm_split(
    const __half* __restrict__ Ah,
    const __half* __restrict__ Bh, const __half* __restrict__ Bl,
    int K, int lda, int ldb, int ldc,
    size_t sA, size_t sB, size_t sC,
    int mode, float alpha,
    float* __restrict__ Cf,
    __half* __restrict__ Ch, __half* __restrict__ Cl,
    const float* __restrict__ bias)
{
    extern __shared__ char dynsmem[];
    const int tid  = threadIdx.x;
    const int lane = tid & 31;
    const int wid  = tid >> 5;
    const int wm   = wid & 1;   // 2 warp rows (64 each)
    const int wn   = wid >> 1;  // 4 warp cols (32 each)

    const int m0 = blockIdx.y * 128;
    const int n0 = blockIdx.x * 128;
    const int z  = blockIdx.z;

    Ah += sA * z;
    Bh += sB * z; Bl += sB * z;

    // ldmatrix per-lane address components (same frag maps as validated R8)
    const int a_row = ((lane >> 3) & 1) * 8 + (lane & 7);
    const int a_k16 = ((lane >> 4) & 1) * 16;          // bytes
    // fused B x4: lanes 0-15 -> hi tile (2 matrices), lanes 16-31 -> lo tile
    const int b_row = lane & 7;
    const int b_k16 = ((lane >> 3) & 1) * 16;          // bytes
    const int b_hl  = ((lane >> 4) & 1) * (B_LO - B_HI);

    float acc[4][4][4];
#pragma unroll
    for (int mt = 0; mt < 4; mt++)
#pragma unroll
        for (int nt = 0; nt < 4; nt++)
#pragma unroll
            for (int k = 0; k < 4; k++) acc[mt][nt][k] = 0.0f;

    const uint32_t sb = smem_u32(dynsmem);
    const int KT = K >> 5;

    // prologue: stages 0,1
    load_stage(sb,           Ah, Bh, Bl, m0, n0, 0,  lda, ldb, tid);
    cp_commit();
    load_stage(sb + STAGE_B, Ah, Bh, Bl, m0, n0, 32, lda, ldb, tid);
    cp_commit();

    int s_cur = 0, s_pf = 2;
    for (int kt = 0; kt < KT; kt++) {
        cp_wait1();              // load(kt) complete; load(kt+1) may be in flight
        __syncthreads();

        if (kt + 2 < KT) {
            load_stage(sb + s_pf * STAGE_B, Ah, Bh, Bl,
                       m0, n0, (kt + 2) * 32, lda, ldb, tid);
        }
        cp_commit();             // uniform: keeps group accounting exact

        const uint32_t base = sb + s_cur * STAGE_B;
#pragma unroll
        for (int ks = 0; ks < 2; ks++) {
            uint32_t bf[4][4];   // [nt]: {Bh k0-7, Bh k8-15, Bl k0-7, Bl k8-15}
#pragma unroll
            for (int nt = 0; nt < 4; nt++) {
                uint32_t ad = base + B_HI + b_hl +
                    (uint32_t)(wn * 32 + nt * 8 + b_row) * ROWB + ks * 32 + b_k16;
                ldsm4(bf[nt], ad);
            }
#pragma unroll
            for (int mt = 0; mt < 4; mt++) {
                uint32_t ah[4];
                uint32_t ad = base +
                    (uint32_t)(wm * 64 + mt * 16 + a_row) * ROWB + ks * 32 + a_k16;
                ldsm4(ah, ad);
#pragma unroll
                for (int nt = 0; nt < 4; nt++) {
                    mma_f16(acc[mt][nt], ah, &bf[nt][0]);   // Ah*Bh
                    mma_f16(acc[mt][nt], ah, &bf[nt][2]);   // Ah*Bl
                }
            }
        }
        s_cur = (s_cur + 1 == NSTAGE) ? 0 : s_cur + 1;
        s_pf  = (s_pf  + 1 == NSTAGE) ? 0 : s_pf  + 1;
    }

    // ---- epilogue
    const int g = lane >> 2, q = lane & 3;
    const int rbase = m0 + wm * 64;
    const int cbase = n0 + wn * 32;

    if (mode == 1) {
        Cf += sC * z;
#pragma unroll
        for (int mt = 0; mt < 4; mt++) {
#pragma unroll
            for (int nt = 0; nt < 4; nt++) {
                int r = rbase + mt * 16 + g;
                int c = cbase + nt * 8 + q * 2;
                float2 v0 = make_float2(alpha * acc[mt][nt][0], alpha * acc[mt][nt][1]);
                float2 v1 = make_float2(alpha * acc[mt][nt][2], alpha * acc[mt][nt][3]);
                *reinterpret_cast<float2*>(&Cf[(size_t)r * ldc + c]) = v0;
                *reinterpret_cast<float2*>(&Cf[(size_t)(r + 8) * ldc + c]) = v1;
            }
        }
    } else {
        Ch += sC * z; Cl += sC * z;
#pragma unroll
        for (int mt = 0; mt < 4; mt++) {
#pragma unroll
            for (int nt = 0; nt < 4; nt++) {
                int r = rbase + mt * 16 + g;
                int c = cbase + nt * 8 + q * 2;
                float b0 = bias[c], b1 = bias[c + 1];
#pragma unroll
                for (int hh = 0; hh < 2; hh++) {
                    float v0 = acc[mt][nt][hh * 2 + 0] + b0;
                    float v1 = acc[mt][nt][hh * 2 + 1] + b1;
                    __half h0 = __float2half_rn(v0);
                    __half h1 = __float2half_rn(v1);
                    __half l0 = __float2half_rn(v0 - __half2float(h0));
                    __half l1 = __float2half_rn(v1 - __half2float(h1));
                    size_t off = (size_t)(r + hh * 8) * ldc + c;
                    *reinterpret_cast<__half2*>(&Ch[off]) = __halves2half2(h0, h1);
                    *reinterpret_cast<__half2*>(&Cl[off]) = __halves2half2(l0, l1);
                }
            }
        }
    }
}

// ---------------------------------------------------------------------------
// fp32 -> fp16 (hi only), 4 elems/thread
// ---------------------------------------------------------------------------
__global__ __launch_bounds__(256) void cvt_f16(
    const float4* __restrict__ x, __half* __restrict__ hi, size_t n4)
{
    size_t i = (size_t)blockIdx.x * 256 + threadIdx.x;
    if (i >= n4) return;
    float4 v = x[i];
    __half2 a = __halves2half2(__float2half_rn(v.x), __float2half_rn(v.y));
    __half2 b = __halves2half2(__float2half_rn(v.z), __float2half_rn(v.w));
    *reinterpret_cast<__half2*>(&hi[i * 4])     = a;
    *reinterpret_cast<__half2*>(&hi[i * 4 + 2]) = b;
}

// ---------------------------------------------------------------------------
// fp32 -> split fp16 (hi + lo), 4 elems/thread
// ---------------------------------------------------------------------------
__global__ __launch_bounds__(256) void split_f16(
    const float4* __restrict__ x, __half* __restrict__ hi,
    __half* __restrict__ lo, size_t n4)
{
    size_t i = (size_t)blockIdx.x * 256 + threadIdx.x;
    if (i >= n4) return;
    float4 v = x[i];
    float vv[4] = {v.x, v.y, v.z, v.w};
    __half h[4], l[4];
#pragma unroll
    for (int j = 0; j < 4; j++) {
        h[j] = __float2half_rn(vv[j]);
        l[j] = __float2half_rn(vv[j] - __half2float(h[j]));
    }
    *reinterpret_cast<__half2*>(&hi[i * 4])     = __halves2half2(h[0], h[1]);
    *reinterpret_cast<__half2*>(&hi[i * 4 + 2]) = __halves2half2(h[2], h[3]);
    *reinterpret_cast<__half2*>(&lo[i * 4])     = __halves2half2(l[0], l[1]);
    *reinterpret_cast<__half2*>(&lo[i * 4 + 2]) = __halves2half2(l[2], l[3]);
}

// ---------------------------------------------------------------------------
// Transpose V slice of qkv (cols [2048,3072)) -> Vt[b][e][s], hi & lo
// ---------------------------------------------------------------------------
__global__ __launch_bounds__(256) void transposeV(
    const __half* __restrict__ qh, const __half* __restrict__ ql,
    __half* __restrict__ vth, __half* __restrict__ vtl)
{
    __shared__ __half th[32][33], tl[32][33];
    int b  = blockIdx.z;
    int s0 = blockIdx.x * 32;
    int e0 = blockIdx.y * 32;
    int tx = threadIdx.x, ty = threadIdx.y;   // 32 x 8
#pragma unroll
    for (int j = 0; j < 4; j++) {
        int s = s0 + ty + j * 8;
        size_t gi = (size_t)(b * SS + s) * FF + 2 * EE + e0 + tx;
        th[ty + j * 8][tx] = qh[gi];
        tl[ty + j * 8][tx] = ql[gi];
    }
    __syncthreads();
#pragma unroll
    for (int j = 0; j < 4; j++) {
        int e = e0 + ty + j * 8;
        size_t go = (size_t)b * EE * SS + (size_t)e * SS + s0 + tx;
        vth[go] = th[tx][ty + j * 8];
        vtl[go] = tl[tx][ty + j * 8];
    }
}

// ---------------------------------------------------------------------------
// Row softmax (fp32 in place) + write fp16 copy for the AV GEMM
// ---------------------------------------------------------------------------
__global__ __launch_bounds__(256) void softmax_h(
    float* __restrict__ attn, __half* __restrict__ ah)
{
    size_t rbase = (size_t)blockIdx.x * SS;
    float* row = attn + rbase;
    __shared__ float red[256];
    const int t = threadIdx.x;

    float vals[8];
    float vmax = -INFINITY;
#pragma unroll
    for (int i = 0; i < 8; i++) {
        vals[i] = row[t + i * 256];
        vmax = fmaxf(vmax, vals[i]);
    }
    red[t] = vmax;
    __syncthreads();
#pragma unroll
    for (int s = 128; s > 0; s >>= 1) {
        if (t < s) red[t] = fmaxf(red[t], red[t + s]);
        __syncthreads();
    }
    vmax = red[0];
    __syncthreads();

    float sum = 0.0f;
#pragma unroll
    for (int i = 0; i < 8; i++) {
        vals[i] = __expf(vals[i] - vmax);
        sum += vals[i];
    }
    red[t] = sum;
    __syncthreads();
#pragma unroll
    for (int s = 128; s > 0; s >>= 1) {
        if (t < s) red[t] += red[t + s];
        __syncthreads();
    }
    const float inv = 1.0f / red[0];
#pragma unroll
    for (int i = 0; i < 8; i++) {
        float v = vals[i] * inv;
        int idx = t + i * 256;
        row[idx] = v;
        ah[rbase + idx] = __float2half_rn(v);
    }
}

// ---------------------------------------------------------------------------
extern "C" void kernel_launch(void* const* d_in, const int* in_sizes, int n_in,
                              void* d_out, int out_size)
{
    const float* X    = (const float*)d_in[0];  // [B,S,E]
    const float* W    = (const float*)d_in[1];  // [3E,E]
    const float* bias = (const float*)d_in[2];  // [3E]

    float* out  = (float*)d_out;                 // [B,S,E]
    float* attn = out + (size_t)BB * SS * EE;    // [B,S,S]

    __half *Xh, *Wh, *Wl, *Qh, *Ql, *Ath, *Vth, *Vtl;
    cudaGetSymbolAddress((void**)&Xh, g_Xh);
    cudaGetSymbolAddress((void**)&Wh, g_Wh);
    cudaGetSymbolAddress((void**)&Wl, g_Wl);
    cudaGetSymbolAddress((void**)&Qh, g_qkv_h);
    cudaGetSymbolAddress((void**)&Ql, g_qkv_l);
    cudaGetSymbolAddress((void**)&Ath, g_attn_h);
    cudaGetSymbolAddress((void**)&Vth, g_vt_h);
    cudaGetSymbolAddress((void**)&Vtl, g_vt_l);

    (void)cudaFuncSetAttribute(gemm_split,
        cudaFuncAttributeMaxDynamicSharedMemorySize, SMEM_DYN);

    // 1) convert X (A-operand: unsplit), split W (B-operand)
    cvt_f16<<<(BB * SS * EE / 4 + 255) / 256, 256>>>(
        (const float4*)X, Xh, (size_t)BB * SS * EE / 4);
    split_f16<<<(FF * EE / 4 + 255) / 256, 256>>>(
        (const float4*)W, Wh, Wl, (size_t)FF * EE / 4);

    // 2) qkv = X @ W^T + bias -> split fp16  [8192,3072]
    gemm_split<<<dim3(FF / 128, (BB * SS) / 128, 1), 256, SMEM_DYN>>>(
        Xh, Wh, Wl,
        EE, EE, EE, FF,
        (size_t)0, (size_t)0, (size_t)0,
        0, 1.0f, nullptr, Qh, Ql, bias);

    // 3) V^T for the AV GEMM (hi+lo)
    transposeV<<<dim3(SS / 32, EE / 32, BB), dim3(32, 8)>>>(Qh, Ql, Vth, Vtl);

    // 4) scores = Q @ K^T / 32 -> fp32 attn slice  (A=Qh unsplit, B=K hi/lo)
    gemm_split<<<dim3(SS / 128, SS / 128, BB), 256, SMEM_DYN>>>(
        Qh, Qh + EE, Ql + EE,
        EE, FF, FF, SS,
        (size_t)SS * FF, (size_t)SS * FF, (size_t)SS * SS,
        1, 1.0f / 32.0f, attn, nullptr, nullptr, nullptr);

    // 5) softmax rows (fp32 in place) + fp16 copy
    softmax_h<<<BB * SS, 256>>>(attn, Ath);

    // 6) out = attn @ Vt^T -> fp32  (A=attn fp16 unsplit, B=Vt hi/lo)
    gemm_split<<<dim3(EE / 128, SS / 128, BB), 256, SMEM_DYN>>>(
        Ath, Vth, Vtl,
        SS, SS, SS, EE,
        (size_t)SS * SS, (size_t)EE * SS, (size_t)SS * EE,
        1, 1.0f, out, nullptr, nullptr, nullptr);
}

// round 10
// speedup vs baseline: 7.3171x; 1.1310x over previous
#include <cuda_runtime.h>
#include <cuda_fp16.h>
#include <math.h>
#include <stdint.h>

#define BB 4
#define SS 2048
#define EE 1024
#define FF 3072   // 3*EE

// ---------------- scratch (fp16 / split-fp16 representations) ----------------
__device__ __half g_Xh[(size_t)BB * SS * EE];
__device__ __half g_Wh[(size_t)FF * EE];
__device__ __half g_Wl[(size_t)FF * EE];
__device__ __half g_qkv_h[(size_t)BB * SS * FF];
__device__ __half g_qkv_l[(size_t)BB * SS * FF];
__device__ __half g_attn_h[(size_t)BB * SS * SS];
__device__ __half g_vt_h[(size_t)BB * EE * SS];

// ---------------- PTX helpers ----------------
__device__ __forceinline__ uint32_t smem_u32(const void* p) {
    return (uint32_t)__cvta_generic_to_shared(p);
}
__device__ __forceinline__ void cp16(uint32_t s, const void* g) {
    asm volatile("cp.async.cg.shared.global [%0], [%1], 16;\n" :: "r"(s), "l"(g));
}
__device__ __forceinline__ void cp_commit() {
    asm volatile("cp.async.commit_group;\n" ::: "memory");
}
__device__ __forceinline__ void cp_wait1() {
    asm volatile("cp.async.wait_group 1;\n" ::: "memory");
}
__device__ __forceinline__ void ldsm4(uint32_t* r, uint32_t a) {
    asm volatile("ldmatrix.sync.aligned.m8n8.x4.shared.b16 {%0,%1,%2,%3}, [%4];"
        : "=r"(r[0]), "=r"(r[1]), "=r"(r[2]), "=r"(r[3]) : "r"(a));
}
__device__ __forceinline__ void mma_f16(float* c, const uint32_t* a, const uint32_t* b) {
    asm volatile("mma.sync.aligned.m16n8k16.row.col.f32.f16.f16.f32 "
        "{%0,%1,%2,%3}, {%4,%5,%6,%7}, {%8,%9}, {%0,%1,%2,%3};"
        : "+f"(c[0]), "+f"(c[1]), "+f"(c[2]), "+f"(c[3])
        : "r"(a[0]), "r"(a[1]), "r"(a[2]), "r"(a[3]), "r"(b[0]), "r"(b[1]));
}

// ---------------- smem tile layout ----------------
// Per stage: Ah[128][40]fp16, Bh[128][40], (Bl[128][40] iff TWOB). Row = 80B
// (5x16B chunks -> (r*5+c) mod 8 walks all banks: conflict-free).
// Only chunks 0..3 (64B = BK=32 fp16) carry data; chunk 4 is pad.
#define ROWB    80
#define TILE_B  10240
#define NSTAGE  3
#define STAGE2  (3 * TILE_B)   // 2-term stage size
#define STAGE1  (2 * TILE_B)   // 1-term stage size

template <int TWOB>
__device__ __forceinline__ void load_stage(
    uint32_t sbase,
    const __half* gAh, const __half* gBh, const __half* gBl,
    int m0, int n0, int k0, int lda, int ldb, int tid)
{
    const int NT = TWOB ? 3 : 2;
#pragma unroll
    for (int i = 0; i < 2 * NT; i++) {
        const int tile = i >> 1;               // 0:Ah 1:Bh (2:Bl)
        int rem = tid + (i & 1) * 256;         // 0..511
        int row = rem >> 2, cc = rem & 3;      // 128 rows x 4 16B-chunks
        uint32_t so = sbase + tile * TILE_B + row * ROWB + cc * 16;
        const __half* gp;
        if (tile == 0) gp = gAh + (size_t)(m0 + row) * lda + k0 + cc * 8;
        else {
            size_t go = (size_t)(n0 + row) * ldb + k0 + cc * 8;
            gp = (tile == 1 ? gBh : gBl) + go;
        }
        cp16(so, gp);
    }
}

// ---------------------------------------------------------------------------
// Split-fp16 GEMM:  C = alpha * (A @ B^T)
//   TWOB=1: C = Ah*Bh + Ah*Bl  (B split hi/lo)
//   TWOB=0: C = Ah*Bh          (plain fp16)
// A: [M,K] fp16, B: [N,K] fp16. K-major, BK=32, 128x128 CTA tiles.
// mode 0: C -> split fp16 (Ch/Cl) with fp32 bias added first.
// mode 1: C -> fp32 Cf, scaled by alpha.
// 3-stage cp.async pipeline, prefetch distance 2 (wait_group 1).
// ---------------------------------------------------------------------------
template <int TWOB>
__global__ __launch_bounds__(256, 2) void gemm_split(
    const __half* __restrict__ Ah,
    const __half* __restrict__ Bh, const __half* __restrict__ Bl,
    int K, int lda, int ldb, int ldc,
    size_t sA, size_t sB, size_t sC,
    int mode, float alpha,
    float* __restrict__ Cf,
    __half* __restrict__ Ch, __half* __restrict__ Cl,
    const float* __restrict__ bias)
{
    extern __shared__ char dynsmem[];
    const int STAGE_B = TWOB ? STAGE2 : STAGE1;
    const int tid  = threadIdx.x;
    const int lane = tid & 31;
    const int wid  = tid >> 5;
    const int wm   = wid & 1;   // 2 warp rows (64 each)
    const int wn   = wid >> 1;  // 4 warp cols (32 each)

    const int m0 = blockIdx.y * 128;
    const int n0 = blockIdx.x * 128;
    const int z  = blockIdx.z;

    Ah += sA * z;
    Bh += sB * z;
    if (TWOB) Bl += sB * z;

    // ldmatrix per-lane address components (validated R8/R9 frag maps)
    const int a_row = ((lane >> 3) & 1) * 8 + (lane & 7);
    const int a_k16 = ((lane >> 4) & 1) * 16;          // bytes
    // TWOB fused B x4: lanes 0-15 -> hi tile, lanes 16-31 -> lo tile
    const int b_row = lane & 7;
    const int b_k16 = ((lane >> 3) & 1) * 16;          // bytes
    const int b_hl  = ((lane >> 4) & 1) * TILE_B;      // hi->lo tile offset
    // 1-term B x4: matrices 0,1 -> nt=2p k0/k8; matrices 2,3 -> nt=2p+1 k0/k8
    const int b1_nt = (lane >> 4) & 1;                 // nt within pair

    float acc[4][4][4];
#pragma unroll
    for (int mt = 0; mt < 4; mt++)
#pragma unroll
        for (int nt = 0; nt < 4; nt++)
#pragma unroll
            for (int k = 0; k < 4; k++) acc[mt][nt][k] = 0.0f;

    const uint32_t sb = smem_u32(dynsmem);
    const int KT = K >> 5;

    // prologue: stages 0,1
    load_stage<TWOB>(sb,           Ah, Bh, Bl, m0, n0, 0,  lda, ldb, tid);
    cp_commit();
    load_stage<TWOB>(sb + STAGE_B, Ah, Bh, Bl, m0, n0, 32, lda, ldb, tid);
    cp_commit();

    int s_cur = 0, s_pf = 2;
    for (int kt = 0; kt < KT; kt++) {
        cp_wait1();              // load(kt) complete; load(kt+1) may be in flight
        __syncthreads();

        if (kt + 2 < KT) {
            load_stage<TWOB>(sb + s_pf * STAGE_B, Ah, Bh, Bl,
                             m0, n0, (kt + 2) * 32, lda, ldb, tid);
        }
        cp_commit();             // uniform: keeps group accounting exact

        const uint32_t base = sb + s_cur * STAGE_B;
#pragma unroll
        for (int ks = 0; ks < 2; ks++) {
            uint32_t bf[4][4];
            if (TWOB) {
                // [nt]: {Bh k0-7, Bh k8-15, Bl k0-7, Bl k8-15}
#pragma unroll
                for (int nt = 0; nt < 4; nt++) {
                    uint32_t ad = base + TILE_B + b_hl +
                        (uint32_t)(wn * 32 + nt * 8 + b_row) * ROWB + ks * 32 + b_k16;
                    ldsm4(bf[nt], ad);
                }
            } else {
                // pair p covers nt=2p,2p+1: one ldsm4 each
#pragma unroll
                for (int p = 0; p < 2; p++) {
                    uint32_t ad = base + TILE_B +
                        (uint32_t)(wn * 32 + (2 * p + b1_nt) * 8 + b_row) * ROWB
                        + ks * 32 + b_k16;
                    ldsm4(bf[p], ad);   // {nt=2p k0, nt=2p k8, nt=2p+1 k0, nt=2p+1 k8}
                }
            }
#pragma unroll
            for (int mt = 0; mt < 4; mt++) {
                uint32_t ah[4];
                uint32_t ad = base +
                    (uint32_t)(wm * 64 + mt * 16 + a_row) * ROWB + ks * 32 + a_k16;
                ldsm4(ah, ad);
                if (TWOB) {
#pragma unroll
                    for (int nt = 0; nt < 4; nt++) {
                        mma_f16(acc[mt][nt], ah, &bf[nt][0]);   // Ah*Bh
                        mma_f16(acc[mt][nt], ah, &bf[nt][2]);   // Ah*Bl
                    }
                } else {
#pragma unroll
                    for (int p = 0; p < 2; p++) {
                        mma_f16(acc[mt][2 * p],     ah, &bf[p][0]);
                        mma_f16(acc[mt][2 * p + 1], ah, &bf[p][2]);
                    }
                }
            }
        }
        s_cur = (s_cur + 1 == NSTAGE) ? 0 : s_cur + 1;
        s_pf  = (s_pf  + 1 == NSTAGE) ? 0 : s_pf  + 1;
    }

    // ---- epilogue
    const int g = lane >> 2, q = lane & 3;
    const int rbase = m0 + wm * 64;
    const int cbase = n0 + wn * 32;

    if (mode == 1) {
        Cf += sC * z;
#pragma unroll
        for (int mt = 0; mt < 4; mt++) {
#pragma unroll
            for (int nt = 0; nt < 4; nt++) {
                int r = rbase + mt * 16 + g;
                int c = cbase + nt * 8 + q * 2;
                float2 v0 = make_float2(alpha * acc[mt][nt][0], alpha * acc[mt][nt][1]);
                float2 v1 = make_float2(alpha * acc[mt][nt][2], alpha * acc[mt][nt][3]);
                *reinterpret_cast<float2*>(&Cf[(size_t)r * ldc + c]) = v0;
                *reinterpret_cast<float2*>(&Cf[(size_t)(r + 8) * ldc + c]) = v1;
            }
        }
    } else {
        Ch += sC * z; Cl += sC * z;
#pragma unroll
        for (int mt = 0; mt < 4; mt++) {
#pragma unroll
            for (int nt = 0; nt < 4; nt++) {
                int r = rbase + mt * 16 + g;
                int c = cbase + nt * 8 + q * 2;
                float b0 = bias[c], b1 = bias[c + 1];
#pragma unroll
                for (int hh = 0; hh < 2; hh++) {
                    float v0 = acc[mt][nt][hh * 2 + 0] + b0;
                    float v1 = acc[mt][nt][hh * 2 + 1] + b1;
                    __half h0 = __float2half_rn(v0);
                    __half h1 = __float2half_rn(v1);
                    __half l0 = __float2half_rn(v0 - __half2float(h0));
                    __half l1 = __float2half_rn(v1 - __half2float(h1));
                    size_t off = (size_t)(r + hh * 8) * ldc + c;
                    *reinterpret_cast<__half2*>(&Ch[off]) = __halves2half2(h0, h1);
                    *reinterpret_cast<__half2*>(&Cl[off]) = __halves2half2(l0, l1);
                }
            }
        }
    }
}

// ---------------------------------------------------------------------------
// fp32 -> fp16, 4 elems/thread
// ---------------------------------------------------------------------------
__global__ __launch_bounds__(256) void cvt_f16(
    const float4* __restrict__ x, __half* __restrict__ hi, size_t n4)
{
    size_t i = (size_t)blockIdx.x * 256 + threadIdx.x;
    if (i >= n4) return;
    float4 v = x[i];
    *reinterpret_cast<__half2*>(&hi[i * 4]) =
        __halves2half2(__float2half_rn(v.x), __float2half_rn(v.y));
    *reinterpret_cast<__half2*>(&hi[i * 4 + 2]) =
        __halves2half2(__float2half_rn(v.z), __float2half_rn(v.w));
}

// ---------------------------------------------------------------------------
// fp32 -> split fp16 (hi + lo), 4 elems/thread
// ---------------------------------------------------------------------------
__global__ __launch_bounds__(256) void split_f16(
    const float4* __restrict__ x, __half* __restrict__ hi,
    __half* __restrict__ lo, size_t n4)
{
    size_t i = (size_t)blockIdx.x * 256 + threadIdx.x;
    if (i >= n4) return;
    float4 v = x[i];
    float vv[4] = {v.x, v.y, v.z, v.w};
    __half h[4], l[4];
#pragma unroll
    for (int j = 0; j < 4; j++) {
        h[j] = __float2half_rn(vv[j]);
        l[j] = __float2half_rn(vv[j] - __half2float(h[j]));
    }
    *reinterpret_cast<__half2*>(&hi[i * 4])     = __halves2half2(h[0], h[1]);
    *reinterpret_cast<__half2*>(&hi[i * 4 + 2]) = __halves2half2(h[2], h[3]);
    *reinterpret_cast<__half2*>(&lo[i * 4])     = __halves2half2(l[0], l[1]);
    *reinterpret_cast<__half2*>(&lo[i * 4 + 2]) = __halves2half2(l[2], l[3]);
}

// ---------------------------------------------------------------------------
// Transpose V slice of qkv (cols [2048,3072)) -> Vt[b][e][s], hi only
// ---------------------------------------------------------------------------
__global__ __launch_bounds__(256) void transposeV(
    const __half* __restrict__ qh, __half* __restrict__ vth)
{
    __shared__ __half th[32][33];
    int b  = blockIdx.z;
    int s0 = blockIdx.x * 32;
    int e0 = blockIdx.y * 32;
    int tx = threadIdx.x, ty = threadIdx.y;   // 32 x 8
#pragma unroll
    for (int j = 0; j < 4; j++) {
        int s = s0 + ty + j * 8;
        th[ty + j * 8][tx] = qh[(size_t)(b * SS + s) * FF + 2 * EE + e0 + tx];
    }
    __syncthreads();
#pragma unroll
    for (int j = 0; j < 4; j++) {
        int e = e0 + ty + j * 8;
        vth[(size_t)b * EE * SS + (size_t)e * SS + s0 + tx] = th[tx][ty + j * 8];
    }
}

// ---------------------------------------------------------------------------
// Row softmax (fp32 in place) + write fp16 copy for the AV GEMM
// ---------------------------------------------------------------------------
__global__ __launch_bounds__(256) void softmax_h(
    float* __restrict__ attn, __half* __restrict__ ah)
{
    size_t rbase = (size_t)blockIdx.x * SS;
    float* row = attn + rbase;
    __shared__ float red[256];
    const int t = threadIdx.x;

    float vals[8];
    float vmax = -INFINITY;
#pragma unroll
    for (int i = 0; i < 8; i++) {
        vals[i] = row[t + i * 256];
        vmax = fmaxf(vmax, vals[i]);
    }
    red[t] = vmax;
    __syncthreads();
#pragma unroll
    for (int s = 128; s > 0; s >>= 1) {
        if (t < s) red[t] = fmaxf(red[t], red[t + s]);
        __syncthreads();
    }
    vmax = red[0];
    __syncthreads();

    float sum = 0.0f;
#pragma unroll
    for (int i = 0; i < 8; i++) {
        vals[i] = __expf(vals[i] - vmax);
        sum += vals[i];
    }
    red[t] = sum;
    __syncthreads();
#pragma unroll
    for (int s = 128; s > 0; s >>= 1) {
        if (t < s) red[t] += red[t + s];
        __syncthreads();
    }
    const float inv = 1.0f / red[0];
#pragma unroll
    for (int i = 0; i < 8; i++) {
        float v = vals[i] * inv;
        int idx = t + i * 256;
        row[idx] = v;
        ah[rbase + idx] = __float2half_rn(v);
    }
}

// ---------------------------------------------------------------------------
extern "C" void kernel_launch(void* const* d_in, const int* in_sizes, int n_in,
                              void* d_out, int out_size)
{
    const float* X    = (const float*)d_in[0];  // [B,S,E]
    const float* W    = (const float*)d_in[1];  // [3E,E]
    const float* bias = (const float*)d_in[2];  // [3E]

    float* out  = (float*)d_out;                 // [B,S,E]
    float* attn = out + (size_t)BB * SS * EE;    // [B,S,S]

    __half *Xh, *Wh, *Wl, *Qh, *Ql, *Ath, *Vth;
    cudaGetSymbolAddress((void**)&Xh, g_Xh);
    cudaGetSymbolAddress((void**)&Wh, g_Wh);
    cudaGetSymbolAddress((void**)&Wl, g_Wl);
    cudaGetSymbolAddress((void**)&Qh, g_qkv_h);
    cudaGetSymbolAddress((void**)&Ql, g_qkv_l);
    cudaGetSymbolAddress((void**)&Ath, g_attn_h);
    cudaGetSymbolAddress((void**)&Vth, g_vt_h);

    (void)cudaFuncSetAttribute(gemm_split<1>,
        cudaFuncAttributeMaxDynamicSharedMemorySize, NSTAGE * STAGE2);
    (void)cudaFuncSetAttribute(gemm_split<0>,
        cudaFuncAttributeMaxDynamicSharedMemorySize, NSTAGE * STAGE1);

    // 1) convert X (A-operand: unsplit), split W (B-operand)
    cvt_f16<<<(BB * SS * EE / 4 + 255) / 256, 256>>>(
        (const float4*)X, Xh, (size_t)BB * SS * EE / 4);
    split_f16<<<(FF * EE / 4 + 255) / 256, 256>>>(
        (const float4*)W, Wh, Wl, (size_t)FF * EE / 4);

    // 2) qkv = X @ W^T + bias -> split fp16  [8192,3072]  (2-term)
    gemm_split<1><<<dim3(FF / 128, (BB * SS) / 128, 1), 256, NSTAGE * STAGE2>>>(
        Xh, Wh, Wl,
        EE, EE, EE, FF,
        (size_t)0, (size_t)0, (size_t)0,
        0, 1.0f, nullptr, Qh, Ql, bias);

    // 3) V^T (hi only) for the AV GEMM
    transposeV<<<dim3(SS / 32, EE / 32, BB), dim3(32, 8)>>>(Qh, Vth);

    // 4) scores = Q @ K^T / 32 -> fp32 attn slice  (A=Qh, B=K hi/lo, 2-term)
    gemm_split<1><<<dim3(SS / 128, SS / 128, BB), 256, NSTAGE * STAGE2>>>(
        Qh, Qh + EE, Ql + EE,
        EE, FF, FF, SS,
        (size_t)SS * FF, (size_t)SS * FF, (size_t)SS * SS,
        1, 1.0f / 32.0f, attn, nullptr, nullptr, nullptr);

    // 5) softmax rows (fp32 in place) + fp16 copy
    softmax_h<<<BB * SS, 256>>>(attn, Ath);

    // 6) out = attn @ Vt^T -> fp32  (plain fp16, 1-term)
    gemm_split<0><<<dim3(EE / 128, SS / 128, BB), 256, NSTAGE * STAGE1>>>(
        Ath, Vth, Vth,
        SS, SS, SS, EE,
        (size_t)SS * SS, (size_t)EE * SS, (size_t)SS * EE,
        1, 1.0f, out, nullptr, nullptr, nullptr);
}

// round 11
// speedup vs baseline: 8.4399x; 1.1534x over previous
#include <cuda_runtime.h>
#include <cuda_fp16.h>
#include <math.h>
#include <stdint.h>

#define BB 4
#define SS 2048
#define EE 1024
#define FF 3072   // 3*EE

// ---------------- scratch (fp16 / split-fp16 representations) ----------------
__device__ __half g_Xh[(size_t)BB * SS * EE];
__device__ __half g_Wh[(size_t)FF * EE];
__device__ __half g_Wl[(size_t)FF * EE];
__device__ __half g_qkv_h[(size_t)BB * SS * FF];
__device__ __half g_attn_h[(size_t)BB * SS * SS];
__device__ __half g_vt_h[(size_t)BB * EE * SS];

// ---------------- PTX helpers ----------------
__device__ __forceinline__ uint32_t smem_u32(const void* p) {
    return (uint32_t)__cvta_generic_to_shared(p);
}
__device__ __forceinline__ void cp16(uint32_t s, const void* g) {
    asm volatile("cp.async.cg.shared.global [%0], [%1], 16;\n" :: "r"(s), "l"(g));
}
__device__ __forceinline__ void cp_commit() {
    asm volatile("cp.async.commit_group;\n" ::: "memory");
}
__device__ __forceinline__ void cp_wait1() {
    asm volatile("cp.async.wait_group 1;\n" ::: "memory");
}
__device__ __forceinline__ void ldsm4(uint32_t* r, uint32_t a) {
    asm volatile("ldmatrix.sync.aligned.m8n8.x4.shared.b16 {%0,%1,%2,%3}, [%4];"
        : "=r"(r[0]), "=r"(r[1]), "=r"(r[2]), "=r"(r[3]) : "r"(a));
}
__device__ __forceinline__ void mma_f16(float* c, const uint32_t* a, const uint32_t* b) {
    asm volatile("mma.sync.aligned.m16n8k16.row.col.f32.f16.f16.f32 "
        "{%0,%1,%2,%3}, {%4,%5,%6,%7}, {%8,%9}, {%0,%1,%2,%3};"
        : "+f"(c[0]), "+f"(c[1]), "+f"(c[2]), "+f"(c[3])
        : "r"(a[0]), "r"(a[1]), "r"(a[2]), "r"(a[3]), "r"(b[0]), "r"(b[1]));
}

// ---------------- smem tile layout ----------------
// Per stage: Ah[128][40]fp16, Bh[128][40], (Bl[128][40] iff TWOB). Row = 80B
// (5x16B chunks -> (r*5+c) mod 8 walks all banks: conflict-free).
// Only chunks 0..3 (64B = BK=32 fp16) carry data; chunk 4 is pad.
#define ROWB    80
#define TILE_B  10240
#define NSTAGE  3
#define STAGE2  (3 * TILE_B)   // 2-term stage size
#define STAGE1  (2 * TILE_B)   // 1-term stage size

template <int TWOB>
__device__ __forceinline__ void load_stage(
    uint32_t sbase,
    const __half* gAh, const __half* gBh, const __half* gBl,
    int m0, int n0, int k0, int lda, int ldb, int tid)
{
    const int NT = TWOB ? 3 : 2;
#pragma unroll
    for (int i = 0; i < 2 * NT; i++) {
        const int tile = i >> 1;               // 0:Ah 1:Bh (2:Bl)
        int rem = tid + (i & 1) * 256;         // 0..511
        int row = rem >> 2, cc = rem & 3;      // 128 rows x 4 16B-chunks
        uint32_t so = sbase + tile * TILE_B + row * ROWB + cc * 16;
        const __half* gp;
        if (tile == 0) gp = gAh + (size_t)(m0 + row) * lda + k0 + cc * 8;
        else {
            size_t go = (size_t)(n0 + row) * ldb + k0 + cc * 8;
            gp = (tile == 1 ? gBh : gBl) + go;
        }
        cp16(so, gp);
    }
}

// ---------------------------------------------------------------------------
// fp16 GEMM:  C = alpha * (A @ B^T)
//   TWOB=1: C = A*Bh + A*Bl  (B split hi/lo)
//   TWOB=0: C = A*Bh         (plain fp16)
// A: [M,K] fp16, B: [N,K] fp16. K-major, BK=32, 128x128 CTA tiles.
// mode 0: C -> fp16 Ch with fp32 bias added first.
// mode 1: C -> fp32 Cf, scaled by alpha.
// 3-stage cp.async pipeline, prefetch distance 2 (wait_group 1).
// ---------------------------------------------------------------------------
template <int TWOB>
__global__ __launch_bounds__(256, 2) void gemm_split(
    const __half* __restrict__ Ah,
    const __half* __restrict__ Bh, const __half* __restrict__ Bl,
    int K, int lda, int ldb, int ldc,
    size_t sA, size_t sB, size_t sC,
    int mode, float alpha,
    float* __restrict__ Cf,
    __half* __restrict__ Ch,
    const float* __restrict__ bias)
{
    extern __shared__ char dynsmem[];
    const int STAGE_B = TWOB ? STAGE2 : STAGE1;
    const int tid  = threadIdx.x;
    const int lane = tid & 31;
    const int wid  = tid >> 5;
    const int wm   = wid & 1;   // 2 warp rows (64 each)
    const int wn   = wid >> 1;  // 4 warp cols (32 each)

    const int m0 = blockIdx.y * 128;
    const int n0 = blockIdx.x * 128;
    const int z  = blockIdx.z;

    Ah += sA * z;
    Bh += sB * z;
    if (TWOB) Bl += sB * z;

    // ldmatrix per-lane address components (validated R8-R10 frag maps)
    const int a_row = ((lane >> 3) & 1) * 8 + (lane & 7);
    const int a_k16 = ((lane >> 4) & 1) * 16;          // bytes
    // TWOB fused B x4: lanes 0-15 -> hi tile, lanes 16-31 -> lo tile
    const int b_row = lane & 7;
    const int b_k16 = ((lane >> 3) & 1) * 16;          // bytes
    const int b_hl  = ((lane >> 4) & 1) * TILE_B;      // hi->lo tile offset
    // 1-term B x4: matrices 0,1 -> nt=2p; matrices 2,3 -> nt=2p+1
    const int b1_nt = (lane >> 4) & 1;                 // nt within pair

    float acc[4][4][4];
#pragma unroll
    for (int mt = 0; mt < 4; mt++)
#pragma unroll
        for (int nt = 0; nt < 4; nt++)
#pragma unroll
            for (int k = 0; k < 4; k++) acc[mt][nt][k] = 0.0f;

    const uint32_t sb = smem_u32(dynsmem);
    const int KT = K >> 5;

    // prologue: stages 0,1
    load_stage<TWOB>(sb,           Ah, Bh, Bl, m0, n0, 0,  lda, ldb, tid);
    cp_commit();
    load_stage<TWOB>(sb + STAGE_B, Ah, Bh, Bl, m0, n0, 32, lda, ldb, tid);
    cp_commit();

    int s_cur = 0, s_pf = 2;
    for (int kt = 0; kt < KT; kt++) {
        cp_wait1();              // load(kt) complete; load(kt+1) may be in flight
        __syncthreads();

        if (kt + 2 < KT) {
            load_stage<TWOB>(sb + s_pf * STAGE_B, Ah, Bh, Bl,
                             m0, n0, (kt + 2) * 32, lda, ldb, tid);
        }
        cp_commit();             // uniform: keeps group accounting exact

        const uint32_t base = sb + s_cur * STAGE_B;
#pragma unroll
        for (int ks = 0; ks < 2; ks++) {
            uint32_t bf[4][4];
            if (TWOB) {
                // [nt]: {Bh k0-7, Bh k8-15, Bl k0-7, Bl k8-15}
#pragma unroll
                for (int nt = 0; nt < 4; nt++) {
                    uint32_t ad = base + TILE_B + b_hl +
                        (uint32_t)(wn * 32 + nt * 8 + b_row) * ROWB + ks * 32 + b_k16;
                    ldsm4(bf[nt], ad);
                }
            } else {
                // pair p covers nt=2p,2p+1: one ldsm4 each
#pragma unroll
                for (int p = 0; p < 2; p++) {
                    uint32_t ad = base + TILE_B +
                        (uint32_t)(wn * 32 + (2 * p + b1_nt) * 8 + b_row) * ROWB
                        + ks * 32 + b_k16;
                    ldsm4(bf[p], ad);   // {nt=2p k0, nt=2p k8, nt=2p+1 k0, nt=2p+1 k8}
                }
            }
#pragma unroll
            for (int mt = 0; mt < 4; mt++) {
                uint32_t ah[4];
                uint32_t ad = base +
                    (uint32_t)(wm * 64 + mt * 16 + a_row) * ROWB + ks * 32 + a_k16;
                ldsm4(ah, ad);
                if (TWOB) {
#pragma unroll
                    for (int nt = 0; nt < 4; nt++) {
                        mma_f16(acc[mt][nt], ah, &bf[nt][0]);   // A*Bh
                        mma_f16(acc[mt][nt], ah, &bf[nt][2]);   // A*Bl
                    }
                } else {
#pragma unroll
                    for (int p = 0; p < 2; p++) {
                        mma_f16(acc[mt][2 * p],     ah, &bf[p][0]);
                        mma_f16(acc[mt][2 * p + 1], ah, &bf[p][2]);
                    }
                }
            }
        }
        s_cur = (s_cur + 1 == NSTAGE) ? 0 : s_cur + 1;
        s_pf  = (s_pf  + 1 == NSTAGE) ? 0 : s_pf  + 1;
    }

    // ---- epilogue
    const int g = lane >> 2, q = lane & 3;
    const int rbase = m0 + wm * 64;
    const int cbase = n0 + wn * 32;

    if (mode == 1) {
        Cf += sC * z;
#pragma unroll
        for (int mt = 0; mt < 4; mt++) {
#pragma unroll
            for (int nt = 0; nt < 4; nt++) {
                int r = rbase + mt * 16 + g;
                int c = cbase + nt * 8 + q * 2;
                float2 v0 = make_float2(alpha * acc[mt][nt][0], alpha * acc[mt][nt][1]);
                float2 v1 = make_float2(alpha * acc[mt][nt][2], alpha * acc[mt][nt][3]);
                *reinterpret_cast<float2*>(&Cf[(size_t)r * ldc + c]) = v0;
                *reinterpret_cast<float2*>(&Cf[(size_t)(r + 8) * ldc + c]) = v1;
            }
        }
    } else {
        Ch += sC * z;
#pragma unroll
        for (int mt = 0; mt < 4; mt++) {
#pragma unroll
            for (int nt = 0; nt < 4; nt++) {
                int r = rbase + mt * 16 + g;
                int c = cbase + nt * 8 + q * 2;
                float b0 = bias[c], b1 = bias[c + 1];
#pragma unroll
                for (int hh = 0; hh < 2; hh++) {
                    float v0 = acc[mt][nt][hh * 2 + 0] + b0;
                    float v1 = acc[mt][nt][hh * 2 + 1] + b1;
                    size_t off = (size_t)(r + hh * 8) * ldc + c;
                    *reinterpret_cast<__half2*>(&Ch[off]) =
                        __halves2half2(__float2half_rn(v0), __float2half_rn(v1));
                }
            }
        }
    }
}

// ---------------------------------------------------------------------------
// fp32 -> fp16, 4 elems/thread
// ---------------------------------------------------------------------------
__global__ __launch_bounds__(256) void cvt_f16(
    const float4* __restrict__ x, __half* __restrict__ hi, size_t n4)
{
    size_t i = (size_t)blockIdx.x * 256 + threadIdx.x;
    if (i >= n4) return;
    float4 v = x[i];
    *reinterpret_cast<__half2*>(&hi[i * 4]) =
        __halves2half2(__float2half_rn(v.x), __float2half_rn(v.y));
    *reinterpret_cast<__half2*>(&hi[i * 4 + 2]) =
        __halves2half2(__float2half_rn(v.z), __float2half_rn(v.w));
}

// ---------------------------------------------------------------------------
// fp32 -> split fp16 (hi + lo), 4 elems/thread
// ---------------------------------------------------------------------------
__global__ __launch_bounds__(256) void split_f16(
    const float4* __restrict__ x, __half* __restrict__ hi,
    __half* __restrict__ lo, size_t n4)
{
    size_t i = (size_t)blockIdx.x * 256 + threadIdx.x;
    if (i >= n4) return;
    float4 v = x[i];
    float vv[4] = {v.x, v.y, v.z, v.w};
    __half h[4], l[4];
#pragma unroll
    for (int j = 0; j < 4; j++) {
        h[j] = __float2half_rn(vv[j]);
        l[j] = __float2half_rn(vv[j] - __half2float(h[j]));
    }
    *reinterpret_cast<__half2*>(&hi[i * 4])     = __halves2half2(h[0], h[1]);
    *reinterpret_cast<__half2*>(&hi[i * 4 + 2]) = __halves2half2(h[2], h[3]);
    *reinterpret_cast<__half2*>(&lo[i * 4])     = __halves2half2(l[0], l[1]);
    *reinterpret_cast<__half2*>(&lo[i * 4 + 2]) = __halves2half2(l[2], l[3]);
}

// ---------------------------------------------------------------------------
// Transpose V slice of qkv (cols [2048,3072)) -> Vt[b][e][s]
// ---------------------------------------------------------------------------
__global__ __launch_bounds__(256) void transposeV(
    const __half* __restrict__ qh, __half* __restrict__ vth)
{
    __shared__ __half th[32][33];
    int b  = blockIdx.z;
    int s0 = blockIdx.x * 32;
    int e0 = blockIdx.y * 32;
    int tx = threadIdx.x, ty = threadIdx.y;   // 32 x 8
#pragma unroll
    for (int j = 0; j < 4; j++) {
        int s = s0 + ty + j * 8;
        th[ty + j * 8][tx] = qh[(size_t)(b * SS + s) * FF + 2 * EE + e0 + tx];
    }
    __syncthreads();
#pragma unroll
    for (int j = 0; j < 4; j++) {
        int e = e0 + ty + j * 8;
        vth[(size_t)b * EE * SS + (size_t)e * SS + s0 + tx] = th[tx][ty + j * 8];
    }
}

// ---------------------------------------------------------------------------
// Row softmax (fp32 in place) + write fp16 copy for the AV GEMM
// ---------------------------------------------------------------------------
__global__ __launch_bounds__(256) void softmax_h(
    float* __restrict__ attn, __half* __restrict__ ah)
{
    size_t rbase = (size_t)blockIdx.x * SS;
    float* row = attn + rbase;
    __shared__ float red[256];
    const int t = threadIdx.x;

    float vals[8];
    float vmax = -INFINITY;
#pragma unroll
    for (int i = 0; i < 8; i++) {
        vals[i] = row[t + i * 256];
        vmax = fmaxf(vmax, vals[i]);
    }
    red[t] = vmax;
    __syncthreads();
#pragma unroll
    for (int s = 128; s > 0; s >>= 1) {
        if (t < s) red[t] = fmaxf(red[t], red[t + s]);
        __syncthreads();
    }
    vmax = red[0];
    __syncthreads();

    float sum = 0.0f;
#pragma unroll
    for (int i = 0; i < 8; i++) {
        vals[i] = __expf(vals[i] - vmax);
        sum += vals[i];
    }
    red[t] = sum;
    __syncthreads();
#pragma unroll
    for (int s = 128; s > 0; s >>= 1) {
        if (t < s) red[t] += red[t + s];
        __syncthreads();
    }
    const float inv = 1.0f / red[0];
#pragma unroll
    for (int i = 0; i < 8; i++) {
        float v = vals[i] * inv;
        int idx = t + i * 256;
        row[idx] = v;
        ah[rbase + idx] = __float2half_rn(v);
    }
}

// ---------------------------------------------------------------------------
extern "C" void kernel_launch(void* const* d_in, const int* in_sizes, int n_in,
                              void* d_out, int out_size)
{
    const float* X    = (const float*)d_in[0];  // [B,S,E]
    const float* W    = (const float*)d_in[1];  // [3E,E]
    const float* bias = (const float*)d_in[2];  // [3E]

    float* out  = (float*)d_out;                 // [B,S,E]
    float* attn = out + (size_t)BB * SS * EE;    // [B,S,S]

    __half *Xh, *Wh, *Wl, *Qh, *Ath, *Vth;
    cudaGetSymbolAddress((void**)&Xh, g_Xh);
    cudaGetSymbolAddress((void**)&Wh, g_Wh);
    cudaGetSymbolAddress((void**)&Wl, g_Wl);
    cudaGetSymbolAddress((void**)&Qh, g_qkv_h);
    cudaGetSymbolAddress((void**)&Ath, g_attn_h);
    cudaGetSymbolAddress((void**)&Vth, g_vt_h);

    (void)cudaFuncSetAttribute(gemm_split<1>,
        cudaFuncAttributeMaxDynamicSharedMemorySize, NSTAGE * STAGE2);
    (void)cudaFuncSetAttribute(gemm_split<0>,
        cudaFuncAttributeMaxDynamicSharedMemorySize, NSTAGE * STAGE1);

    // 1) convert X (A-operand: unsplit), split W (B-operand)
    cvt_f16<<<(BB * SS * EE / 4 + 255) / 256, 256>>>(
        (const float4*)X, Xh, (size_t)BB * SS * EE / 4);
    split_f16<<<(FF * EE / 4 + 255) / 256, 256>>>(
        (const float4*)W, Wh, Wl, (size_t)FF * EE / 4);

    // 2) qkv = X @ W^T + bias -> fp16  [8192,3072]  (2-term: W split)
    gemm_split<1><<<dim3(FF / 128, (BB * SS) / 128, 1), 256, NSTAGE * STAGE2>>>(
        Xh, Wh, Wl,
        EE, EE, EE, FF,
        (size_t)0, (size_t)0, (size_t)0,
        0, 1.0f, nullptr, Qh, bias);

    // 3) V^T for the AV GEMM
    transposeV<<<dim3(SS / 32, EE / 32, BB), dim3(32, 8)>>>(Qh, Vth);

    // 4) scores = Q @ K^T / 32 -> fp32 attn slice  (plain fp16, 1-term)
    gemm_split<0><<<dim3(SS / 128, SS / 128, BB), 256, NSTAGE * STAGE1>>>(
        Qh, Qh + EE, Qh + EE,
        EE, FF, FF, SS,
        (size_t)SS * FF, (size_t)SS * FF, (size_t)SS * SS,
        1, 1.0f / 32.0f, attn, nullptr, nullptr);

    // 5) softmax rows (fp32 in place) + fp16 copy
    softmax_h<<<BB * SS, 256>>>(attn, Ath);

    // 6) out = attn @ Vt^T -> fp32  (plain fp16, 1-term)
    gemm_split<0><<<dim3(EE / 128, SS / 128, BB), 256, NSTAGE * STAGE1>>>(
        Ath, Vth, Vth,
        SS, SS, SS, EE,
        (size_t)SS * SS, (size_t)EE * SS, (size_t)SS * EE,
        1, 1.0f, out, nullptr, nullptr);
}

// round 12
// speedup vs baseline: 10.3625x; 1.2278x over previous
#include <cuda_runtime.h>
#include <cuda_fp16.h>
#include <math.h>
#include <stdint.h>

#define BB 4
#define SS 2048
#define EE 1024
#define FF 3072   // 3*EE

// ---------------- scratch (fp16 representations) ----------------
__device__ __half g_Xh[(size_t)BB * SS * EE];
__device__ __half g_Wh[(size_t)FF * EE];
__device__ __half g_qkv_h[(size_t)BB * SS * FF];
__device__ __half g_attn_h[(size_t)BB * SS * SS];
__device__ __half g_vt_h[(size_t)BB * EE * SS];

// ---------------- PTX helpers ----------------
__device__ __forceinline__ uint32_t smem_u32(const void* p) {
    return (uint32_t)__cvta_generic_to_shared(p);
}
__device__ __forceinline__ void cp16(uint32_t s, const void* g) {
    asm volatile("cp.async.cg.shared.global [%0], [%1], 16;\n" :: "r"(s), "l"(g));
}
__device__ __forceinline__ void cp_commit() {
    asm volatile("cp.async.commit_group;\n" ::: "memory");
}
__device__ __forceinline__ void cp_wait1() {
    asm volatile("cp.async.wait_group 1;\n" ::: "memory");
}
__device__ __forceinline__ void ldsm4(uint32_t* r, uint32_t a) {
    asm volatile("ldmatrix.sync.aligned.m8n8.x4.shared.b16 {%0,%1,%2,%3}, [%4];"
        : "=r"(r[0]), "=r"(r[1]), "=r"(r[2]), "=r"(r[3]) : "r"(a));
}
__device__ __forceinline__ void mma_f16(float* c, const uint32_t* a, const uint32_t* b) {
    asm volatile("mma.sync.aligned.m16n8k16.row.col.f32.f16.f16.f32 "
        "{%0,%1,%2,%3}, {%4,%5,%6,%7}, {%8,%9}, {%0,%1,%2,%3};"
        : "+f"(c[0]), "+f"(c[1]), "+f"(c[2]), "+f"(c[3])
        : "r"(a[0]), "r"(a[1]), "r"(a[2]), "r"(a[3]), "r"(b[0]), "r"(b[1]));
}

// ---------------- smem tile layout ----------------
// Per stage: A[128][40]fp16, B[128][40]. Row = 80B (5x16B chunks ->
// (r*5+c) mod 8 walks all banks: conflict-free ldmatrix/stores).
// Only chunks 0..3 (64B = BK=32 fp16) carry data; chunk 4 is pad.
#define ROWB    80
#define TILE_B  10240
#define NSTAGE  3
#define STAGE_B (2 * TILE_B)          // 20480
#define SMEM_DYN (NSTAGE * STAGE_B)   // 61440

__device__ __forceinline__ void load_stage(
    uint32_t sbase, const __half* gA, const __half* gB,
    int m0, int n0, int k0, int lda, int ldb, int tid)
{
#pragma unroll
    for (int i = 0; i < 4; i++) {
        const int tile = i >> 1;               // 0:A 1:B
        int rem = tid + (i & 1) * 256;         // 0..511
        int row = rem >> 2, cc = rem & 3;      // 128 rows x 4 16B-chunks
        uint32_t so = sbase + tile * TILE_B + row * ROWB + cc * 16;
        const __half* gp = (tile == 0)
            ? gA + (size_t)(m0 + row) * lda + k0 + cc * 8
            : gB + (size_t)(n0 + row) * ldb + k0 + cc * 8;
        cp16(so, gp);
    }
}

// ---------------------------------------------------------------------------
// fp16 GEMM:  C = alpha * (A @ B^T)
// A: [M,K] fp16, B: [N,K] fp16. K-major, BK=32, 128x128 CTA tiles.
// mode 0: C -> fp16 Ch with fp32 bias added first.
// mode 1: C -> fp32 Cf, scaled by alpha.
// 3-stage cp.async pipeline, prefetch distance 2 (wait_group 1).
// ---------------------------------------------------------------------------
__global__ __launch_bounds__(256, 2) void gemm_f16(
    const __half* __restrict__ Ah, const __half* __restrict__ Bh,
    int K, int lda, int ldb, int ldc,
    size_t sA, size_t sB, size_t sC,
    int mode, float alpha,
    float* __restrict__ Cf,
    __half* __restrict__ Ch,
    const float* __restrict__ bias)
{
    extern __shared__ char dynsmem[];
    const int tid  = threadIdx.x;
    const int lane = tid & 31;
    const int wid  = tid >> 5;
    const int wm   = wid & 1;   // 2 warp rows (64 each)
    const int wn   = wid >> 1;  // 4 warp cols (32 each)

    const int m0 = blockIdx.y * 128;
    const int n0 = blockIdx.x * 128;
    const int z  = blockIdx.z;

    Ah += sA * z;
    Bh += sB * z;

    // ldmatrix per-lane address components (validated R8-R11 frag maps)
    const int a_row = ((lane >> 3) & 1) * 8 + (lane & 7);
    const int a_k16 = ((lane >> 4) & 1) * 16;          // bytes
    // B x4: matrices 0,1 -> nt=2p; matrices 2,3 -> nt=2p+1
    const int b_row = lane & 7;
    const int b_k16 = ((lane >> 3) & 1) * 16;          // bytes
    const int b1_nt = (lane >> 4) & 1;                 // nt within pair

    float acc[4][4][4];
#pragma unroll
    for (int mt = 0; mt < 4; mt++)
#pragma unroll
        for (int nt = 0; nt < 4; nt++)
#pragma unroll
            for (int k = 0; k < 4; k++) acc[mt][nt][k] = 0.0f;

    const uint32_t sb = smem_u32(dynsmem);
    const int KT = K >> 5;

    // prologue: stages 0,1
    load_stage(sb,           Ah, Bh, m0, n0, 0,  lda, ldb, tid);
    cp_commit();
    load_stage(sb + STAGE_B, Ah, Bh, m0, n0, 32, lda, ldb, tid);
    cp_commit();

    int s_cur = 0, s_pf = 2;
    for (int kt = 0; kt < KT; kt++) {
        cp_wait1();              // load(kt) complete; load(kt+1) may be in flight
        __syncthreads();

        if (kt + 2 < KT) {
            load_stage(sb + s_pf * STAGE_B, Ah, Bh,
                       m0, n0, (kt + 2) * 32, lda, ldb, tid);
        }
        cp_commit();             // uniform: keeps group accounting exact

        const uint32_t base = sb + s_cur * STAGE_B;
#pragma unroll
        for (int ks = 0; ks < 2; ks++) {
            uint32_t bf[2][4];
#pragma unroll
            for (int p = 0; p < 2; p++) {
                uint32_t ad = base + TILE_B +
                    (uint32_t)(wn * 32 + (2 * p + b1_nt) * 8 + b_row) * ROWB
                    + ks * 32 + b_k16;
                ldsm4(bf[p], ad);   // {nt=2p k0, nt=2p k8, nt=2p+1 k0, nt=2p+1 k8}
            }
#pragma unroll
            for (int mt = 0; mt < 4; mt++) {
                uint32_t ah[4];
                uint32_t ad = base +
                    (uint32_t)(wm * 64 + mt * 16 + a_row) * ROWB + ks * 32 + a_k16;
                ldsm4(ah, ad);
#pragma unroll
                for (int p = 0; p < 2; p++) {
                    mma_f16(acc[mt][2 * p],     ah, &bf[p][0]);
                    mma_f16(acc[mt][2 * p + 1], ah, &bf[p][2]);
                }
            }
        }
        s_cur = (s_cur + 1 == NSTAGE) ? 0 : s_cur + 1;
        s_pf  = (s_pf  + 1 == NSTAGE) ? 0 : s_pf  + 1;
    }

    // ---- epilogue
    const int g = lane >> 2, q = lane & 3;
    const int rbase = m0 + wm * 64;
    const int cbase = n0 + wn * 32;

    if (mode == 1) {
        Cf += sC * z;
#pragma unroll
        for (int mt = 0; mt < 4; mt++) {
#pragma unroll
            for (int nt = 0; nt < 4; nt++) {
                int r = rbase + mt * 16 + g;
                int c = cbase + nt * 8 + q * 2;
                float2 v0 = make_float2(alpha * acc[mt][nt][0], alpha * acc[mt][nt][1]);
                float2 v1 = make_float2(alpha * acc[mt][nt][2], alpha * acc[mt][nt][3]);
                *reinterpret_cast<float2*>(&Cf[(size_t)r * ldc + c]) = v0;
                *reinterpret_cast<float2*>(&Cf[(size_t)(r + 8) * ldc + c]) = v1;
            }
        }
    } else {
        Ch += sC * z;
#pragma unroll
        for (int mt = 0; mt < 4; mt++) {
#pragma unroll
            for (int nt = 0; nt < 4; nt++) {
                int r = rbase + mt * 16 + g;
                int c = cbase + nt * 8 + q * 2;
                float b0 = bias[c], b1 = bias[c + 1];
#pragma unroll
                for (int hh = 0; hh < 2; hh++) {
                    float v0 = acc[mt][nt][hh * 2 + 0] + b0;
                    float v1 = acc[mt][nt][hh * 2 + 1] + b1;
                    size_t off = (size_t)(r + hh * 8) * ldc + c;
                    *reinterpret_cast<__half2*>(&Ch[off]) =
                        __halves2half2(__float2half_rn(v0), __float2half_rn(v1));
                }
            }
        }
    }
}

// ---------------------------------------------------------------------------
// fp32 -> fp16, 4 elems/thread
// ---------------------------------------------------------------------------
__global__ __launch_bounds__(256) void cvt_f16(
    const float4* __restrict__ x, __half* __restrict__ hi, size_t n4)
{
    size_t i = (size_t)blockIdx.x * 256 + threadIdx.x;
    if (i >= n4) return;
    float4 v = x[i];
    *reinterpret_cast<__half2*>(&hi[i * 4]) =
        __halves2half2(__float2half_rn(v.x), __float2half_rn(v.y));
    *reinterpret_cast<__half2*>(&hi[i * 4 + 2]) =
        __halves2half2(__float2half_rn(v.z), __float2half_rn(v.w));
}

// ---------------------------------------------------------------------------
// Transpose V slice of qkv (cols [2048,3072)) -> Vt[b][e][s]
// ---------------------------------------------------------------------------
__global__ __launch_bounds__(256) void transposeV(
    const __half* __restrict__ qh, __half* __restrict__ vth)
{
    __shared__ __half th[32][33];
    int b  = blockIdx.z;
    int s0 = blockIdx.x * 32;
    int e0 = blockIdx.y * 32;
    int tx = threadIdx.x, ty = threadIdx.y;   // 32 x 8
#pragma unroll
    for (int j = 0; j < 4; j++) {
        int s = s0 + ty + j * 8;
        th[ty + j * 8][tx] = qh[(size_t)(b * SS + s) * FF + 2 * EE + e0 + tx];
    }
    __syncthreads();
#pragma unroll
    for (int j = 0; j < 4; j++) {
        int e = e0 + ty + j * 8;
        vth[(size_t)b * EE * SS + (size_t)e * SS + s0 + tx] = th[tx][ty + j * 8];
    }
}

// ---------------------------------------------------------------------------
// Row softmax (fp32 in place) + write fp16 copy for the AV GEMM
// ---------------------------------------------------------------------------
__global__ __launch_bounds__(256) void softmax_h(
    float* __restrict__ attn, __half* __restrict__ ah)
{
    size_t rbase = (size_t)blockIdx.x * SS;
    float* row = attn + rbase;
    __shared__ float red[256];
    const int t = threadIdx.x;

    float vals[8];
    float vmax = -INFINITY;
#pragma unroll
    for (int i = 0; i < 8; i++) {
        vals[i] = row[t + i * 256];
        vmax = fmaxf(vmax, vals[i]);
    }
    red[t] = vmax;
    __syncthreads();
#pragma unroll
    for (int s = 128; s > 0; s >>= 1) {
        if (t < s) red[t] = fmaxf(red[t], red[t + s]);
        __syncthreads();
    }
    vmax = red[0];
    __syncthreads();

    float sum = 0.0f;
#pragma unroll
    for (int i = 0; i < 8; i++) {
        vals[i] = __expf(vals[i] - vmax);
        sum += vals[i];
    }
    red[t] = sum;
    __syncthreads();
#pragma unroll
    for (int s = 128; s > 0; s >>= 1) {
        if (t < s) red[t] += red[t + s];
        __syncthreads();
    }
    const float inv = 1.0f / red[0];
#pragma unroll
    for (int i = 0; i < 8; i++) {
        float v = vals[i] * inv;
        int idx = t + i * 256;
        row[idx] = v;
        ah[rbase + idx] = __float2half_rn(v);
    }
}

// ---------------------------------------------------------------------------
extern "C" void kernel_launch(void* const* d_in, const int* in_sizes, int n_in,
                              void* d_out, int out_size)
{
    const float* X    = (const float*)d_in[0];  // [B,S,E]
    const float* W    = (const float*)d_in[1];  // [3E,E]
    const float* bias = (const float*)d_in[2];  // [3E]

    float* out  = (float*)d_out;                 // [B,S,E]
    float* attn = out + (size_t)BB * SS * EE;    // [B,S,S]

    __half *Xh, *Wh, *Qh, *Ath, *Vth;
    cudaGetSymbolAddress((void**)&Xh, g_Xh);
    cudaGetSymbolAddress((void**)&Wh, g_Wh);
    cudaGetSymbolAddress((void**)&Qh, g_qkv_h);
    cudaGetSymbolAddress((void**)&Ath, g_attn_h);
    cudaGetSymbolAddress((void**)&Vth, g_vt_h);

    (void)cudaFuncSetAttribute(gemm_f16,
        cudaFuncAttributeMaxDynamicSharedMemorySize, SMEM_DYN);

    // 1) convert X and W to fp16
    cvt_f16<<<(BB * SS * EE / 4 + 255) / 256, 256>>>(
        (const float4*)X, Xh, (size_t)BB * SS * EE / 4);
    cvt_f16<<<(FF * EE / 4 + 255) / 256, 256>>>(
        (const float4*)W, Wh, (size_t)FF * EE / 4);

    // 2) qkv = X @ W^T + bias -> fp16  [8192,3072]
    gemm_f16<<<dim3(FF / 128, (BB * SS) / 128, 1), 256, SMEM_DYN>>>(
        Xh, Wh,
        EE, EE, EE, FF,
        (size_t)0, (size_t)0, (size_t)0,
        0, 1.0f, nullptr, Qh, bias);

    // 3) V^T for the AV GEMM
    transposeV<<<dim3(SS / 32, EE / 32, BB), dim3(32, 8)>>>(Qh, Vth);

    // 4) scores = Q @ K^T / 32 -> fp32 attn slice
    gemm_f16<<<dim3(SS / 128, SS / 128, BB), 256, SMEM_DYN>>>(
        Qh, Qh + EE,
        EE, FF, FF, SS,
        (size_t)SS * FF, (size_t)SS * FF, (size_t)SS * SS,
        1, 1.0f / 32.0f, attn, nullptr, nullptr);

    // 5) softmax rows (fp32 in place) + fp16 copy
    softmax_h<<<BB * SS, 256>>>(attn, Ath);

    // 6) out = attn @ Vt^T -> fp32
    gemm_f16<<<dim3(EE / 128, SS / 128, BB), 256, SMEM_DYN>>>(
        Ath, Vth,
        SS, SS, SS, EE,
        (size_t)SS * SS, (size_t)EE * SS, (size_t)SS * EE,
        1, 1.0f, out, nullptr, nullptr);
}

// round 13
// speedup vs baseline: 11.8114x; 1.1398x over previous
#include <cuda_runtime.h>
#include <cuda_fp16.h>
#include <math.h>
#include <stdint.h>

#define BB 4
#define SS 2048
#define EE 1024
#define FF 3072   // 3*EE

// ---------------- scratch (fp16 representations) ----------------
__device__ __half g_Xh[(size_t)BB * SS * EE];
__device__ __half g_Wh[(size_t)FF * EE];
__device__ __half g_qkv_h[(size_t)BB * SS * FF];
__device__ __half g_attn_h[(size_t)BB * SS * SS];

// ---------------- PTX helpers ----------------
__device__ __forceinline__ uint32_t smem_u32(const void* p) {
    return (uint32_t)__cvta_generic_to_shared(p);
}
__device__ __forceinline__ void cp16(uint32_t s, const void* g) {
    asm volatile("cp.async.cg.shared.global [%0], [%1], 16;\n" :: "r"(s), "l"(g));
}
__device__ __forceinline__ void cp_commit() {
    asm volatile("cp.async.commit_group;\n" ::: "memory");
}
__device__ __forceinline__ void cp_wait0() {
    asm volatile("cp.async.wait_group 0;\n" ::: "memory");
}
__device__ __forceinline__ void ldsm4(uint32_t* r, uint32_t a) {
    asm volatile("ldmatrix.sync.aligned.m8n8.x4.shared.b16 {%0,%1,%2,%3}, [%4];"
        : "=r"(r[0]), "=r"(r[1]), "=r"(r[2]), "=r"(r[3]) : "r"(a));
}
__device__ __forceinline__ void ldsm4t(uint32_t* r, uint32_t a) {
    asm volatile("ldmatrix.sync.aligned.m8n8.x4.trans.shared.b16 {%0,%1,%2,%3}, [%4];"
        : "=r"(r[0]), "=r"(r[1]), "=r"(r[2]), "=r"(r[3]) : "r"(a));
}
__device__ __forceinline__ void mma_f16(float* c, const uint32_t* a, const uint32_t* b) {
    asm volatile("mma.sync.aligned.m16n8k16.row.col.f32.f16.f16.f32 "
        "{%0,%1,%2,%3}, {%4,%5,%6,%7}, {%8,%9}, {%0,%1,%2,%3};"
        : "+f"(c[0]), "+f"(c[1]), "+f"(c[2]), "+f"(c[3])
        : "r"(a[0]), "r"(a[1]), "r"(a[2]), "r"(a[3]), "r"(b[0]), "r"(b[1]));
}

// ---------------- smem tile layout (BK = 64) ----------------
// A tile: 128 rows x 144B (128B data = 64 fp16 + 16B pad). (r*9+c) mod 8
// walks all banks -> conflict-free ldmatrix/stores.
// B tile non-trans: same as A (B stored [N][K]).
// B tile trans (native V [K][N]): 64 k-rows x 272B (256B data = 128 fp16 +
// 16B pad). 17 chunks/row, 17 mod 8 = 1 -> 8 consecutive k-rows at one
// n-chunk hit 8 distinct banks: conflict-free ldmatrix.trans.
#define ROWA     144
#define ROWBT    272
#define TILE_A   18432            // 128*144
#define TILE_B0  18432
#define TILE_B1  17408            // 64*272
#define STAGE0   (TILE_A + TILE_B0)   // 36864
#define STAGE1   (TILE_A + TILE_B1)   // 35840

template <int TRANSB>
__device__ __forceinline__ void load_stage(
    uint32_t sbase, const __half* gA, const __half* gB,
    int m0, int n0, int k0, int lda, int ldb, int tid)
{
    // A: 128 rows x 8 chunks = 1024 chunks over 256 threads
#pragma unroll
    for (int j = 0; j < 4; j++) {
        int ca = tid + j * 256;
        int row = ca >> 3, c = ca & 7;
        cp16(sbase + row * ROWA + c * 16,
             gA + (size_t)(m0 + row) * lda + k0 + c * 8);
    }
    if (!TRANSB) {
        // B [N][K]: 128 rows x 8 chunks
#pragma unroll
        for (int j = 0; j < 4; j++) {
            int cb = tid + j * 256;
            int row = cb >> 3, c = cb & 7;
            cp16(sbase + TILE_A + row * ROWA + c * 16,
                 gB + (size_t)(n0 + row) * ldb + k0 + c * 8);
        }
    } else {
        // B [K][N] native: 64 k-rows x 16 chunks
#pragma unroll
        for (int j = 0; j < 4; j++) {
            int cb = tid + j * 256;
            int row = cb >> 4, c = cb & 15;
            cp16(sbase + TILE_A + row * ROWBT + c * 16,
                 gB + (size_t)(k0 + row) * ldb + n0 + c * 8);
        }
    }
}

// ---------------------------------------------------------------------------
// fp16 GEMM:  C = alpha * (A @ op(B))
//   TRANSB=0: B stored [N,K] row-major (C = A @ B^T)
//   TRANSB=1: B stored [K,N] row-major (C = A @ B), via ldmatrix.trans
// A: [M,K] fp16. BK=64, 128x128 CTA tiles, 8 warps x (64x32).
// mode 0: C -> fp16 Ch with fp32 bias added first.
// mode 1: C -> fp32 Cf, scaled by alpha.
// 2-stage cp.async pipeline (wait_group 0; prefetch overlaps compute).
// ---------------------------------------------------------------------------
template <int TRANSB>
__global__ __launch_bounds__(256, 2) void gemm_f16(
    const __half* __restrict__ Ah, const __half* __restrict__ Bh,
    int K, int lda, int ldb, int ldc,
    size_t sA, size_t sB, size_t sC,
    int mode, float alpha,
    float* __restrict__ Cf,
    __half* __restrict__ Ch,
    const float* __restrict__ bias)
{
    extern __shared__ char dynsmem[];
    const int STAGE_B = TRANSB ? STAGE1 : STAGE0;
    const int tid  = threadIdx.x;
    const int lane = tid & 31;
    const int wid  = tid >> 5;
    const int wm   = wid & 1;   // 2 warp rows (64 each)
    const int wn   = wid >> 1;  // 4 warp cols (32 each)

    const int m0 = blockIdx.y * 128;
    const int n0 = blockIdx.x * 128;
    const int z  = blockIdx.z;

    Ah += sA * z;
    Bh += sB * z;

    // ldmatrix per-lane address components (frag maps validated R8-R12)
    const int a_row = ((lane >> 3) & 1) * 8 + (lane & 7);
    const int a_k16 = ((lane >> 4) & 1) * 16;          // bytes within 32B k-slice
    // non-trans B: matrices {nt k0, nt k8, nt+1 k0, nt+1 k8}
    const int b_row = lane & 7;
    const int b_k16 = ((lane >> 3) & 1) * 16;
    const int b1_nt = (lane >> 4) & 1;
    // trans B: same matrix order from native [K][N] tile
    const int bt_row = ((lane >> 3) & 1) * 8 + (lane & 7);  // k within slice
    const int bt_c   = (lane >> 4) & 1;                     // n-chunk select

    float acc[4][4][4];
#pragma unroll
    for (int mt = 0; mt < 4; mt++)
#pragma unroll
        for (int nt = 0; nt < 4; nt++)
#pragma unroll
            for (int k = 0; k < 4; k++) acc[mt][nt][k] = 0.0f;

    const uint32_t sb = smem_u32(dynsmem);
    const int KT = K >> 6;   // BK = 64

    // prologue: stage 0
    load_stage<TRANSB>(sb, Ah, Bh, m0, n0, 0, lda, ldb, tid);
    cp_commit();

    for (int kt = 0; kt < KT; kt++) {
        cp_wait0();              // load(kt) complete (only it is outstanding)
        __syncthreads();         // also proves all warps left compute(kt-1)

        if (kt + 1 < KT) {       // prefetch overlaps compute(kt)
            load_stage<TRANSB>(sb + ((kt + 1) & 1) * STAGE_B, Ah, Bh,
                               m0, n0, (kt + 1) * 64, lda, ldb, tid);
            cp_commit();
        }

        const uint32_t base = sb + (kt & 1) * STAGE_B;
#pragma unroll
        for (int ks = 0; ks < 4; ks++) {
            uint32_t bf[2][4];
            if (!TRANSB) {
#pragma unroll
                for (int p = 0; p < 2; p++) {
                    uint32_t ad = base + TILE_A +
                        (uint32_t)(wn * 32 + (2 * p + b1_nt) * 8 + b_row) * ROWA
                        + ks * 32 + b_k16;
                    ldsm4(bf[p], ad);
                }
            } else {
#pragma unroll
                for (int p = 0; p < 2; p++) {
                    uint32_t ad = base + TILE_A +
                        (uint32_t)(ks * 16 + bt_row) * ROWBT
                        + (uint32_t)(wn * 4 + p * 2 + bt_c) * 16;
                    ldsm4t(bf[p], ad);
                }
            }
#pragma unroll
            for (int mt = 0; mt < 4; mt++) {
                uint32_t ah[4];
                uint32_t ad = base +
                    (uint32_t)(wm * 64 + mt * 16 + a_row) * ROWA + ks * 32 + a_k16;
                ldsm4(ah, ad);
#pragma unroll
                for (int p = 0; p < 2; p++) {
                    mma_f16(acc[mt][2 * p],     ah, &bf[p][0]);
                    mma_f16(acc[mt][2 * p + 1], ah, &bf[p][2]);
                }
            }
        }
    }

    // ---- epilogue
    const int g = lane >> 2, q = lane & 3;
    const int rbase = m0 + wm * 64;
    const int cbase = n0 + wn * 32;

    if (mode == 1) {
        Cf += sC * z;
#pragma unroll
        for (int mt = 0; mt < 4; mt++) {
#pragma unroll
            for (int nt = 0; nt < 4; nt++) {
                int r = rbase + mt * 16 + g;
                int c = cbase + nt * 8 + q * 2;
                float2 v0 = make_float2(alpha * acc[mt][nt][0], alpha * acc[mt][nt][1]);
                float2 v1 = make_float2(alpha * acc[mt][nt][2], alpha * acc[mt][nt][3]);
                *reinterpret_cast<float2*>(&Cf[(size_t)r * ldc + c]) = v0;
                *reinterpret_cast<float2*>(&Cf[(size_t)(r + 8) * ldc + c]) = v1;
            }
        }
    } else {
        Ch += sC * z;
#pragma unroll
        for (int mt = 0; mt < 4; mt++) {
#pragma unroll
            for (int nt = 0; nt < 4; nt++) {
                int r = rbase + mt * 16 + g;
                int c = cbase + nt * 8 + q * 2;
                float b0 = bias[c], b1 = bias[c + 1];
#pragma unroll
                for (int hh = 0; hh < 2; hh++) {
                    float v0 = acc[mt][nt][hh * 2 + 0] + b0;
                    float v1 = acc[mt][nt][hh * 2 + 1] + b1;
                    size_t off = (size_t)(r + hh * 8) * ldc + c;
                    *reinterpret_cast<__half2*>(&Ch[off]) =
                        __halves2half2(__float2half_rn(v0), __float2half_rn(v1));
                }
            }
        }
    }
}

// ---------------------------------------------------------------------------
// fp32 -> fp16, 4 elems/thread
// ---------------------------------------------------------------------------
__global__ __launch_bounds__(256) void cvt_f16(
    const float4* __restrict__ x, __half* __restrict__ hi, size_t n4)
{
    size_t i = (size_t)blockIdx.x * 256 + threadIdx.x;
    if (i >= n4) return;
    float4 v = x[i];
    *reinterpret_cast<__half2*>(&hi[i * 4]) =
        __halves2half2(__float2half_rn(v.x), __float2half_rn(v.y));
    *reinterpret_cast<__half2*>(&hi[i * 4 + 2]) =
        __halves2half2(__float2half_rn(v.z), __float2half_rn(v.w));
}

// ---------------------------------------------------------------------------
// Row softmax (fp32 in place) + write fp16 copy for the AV GEMM
// ---------------------------------------------------------------------------
__global__ __launch_bounds__(256) void softmax_h(
    float* __restrict__ attn, __half* __restrict__ ah)
{
    size_t rbase = (size_t)blockIdx.x * SS;
    float* row = attn + rbase;
    __shared__ float red[256];
    const int t = threadIdx.x;

    float vals[8];
    float vmax = -INFINITY;
#pragma unroll
    for (int i = 0; i < 8; i++) {
        vals[i] = row[t + i * 256];
        vmax = fmaxf(vmax, vals[i]);
    }
    red[t] = vmax;
    __syncthreads();
#pragma unroll
    for (int s = 128; s > 0; s >>= 1) {
        if (t < s) red[t] = fmaxf(red[t], red[t + s]);
        __syncthreads();
    }
    vmax = red[0];
    __syncthreads();

    float sum = 0.0f;
#pragma unroll
    for (int i = 0; i < 8; i++) {
        vals[i] = __expf(vals[i] - vmax);
        sum += vals[i];
    }
    red[t] = sum;
    __syncthreads();
#pragma unroll
    for (int s = 128; s > 0; s >>= 1) {
        if (t < s) red[t] += red[t + s];
        __syncthreads();
    }
    const float inv = 1.0f / red[0];
#pragma unroll
    for (int i = 0; i < 8; i++) {
        float v = vals[i] * inv;
        int idx = t + i * 256;
        row[idx] = v;
        ah[rbase + idx] = __float2half_rn(v);
    }
}

// ---------------------------------------------------------------------------
extern "C" void kernel_launch(void* const* d_in, const int* in_sizes, int n_in,
                              void* d_out, int out_size)
{
    const float* X    = (const float*)d_in[0];  // [B,S,E]
    const float* W    = (const float*)d_in[1];  // [3E,E]
    const float* bias = (const float*)d_in[2];  // [3E]

    float* out  = (float*)d_out;                 // [B,S,E]
    float* attn = out + (size_t)BB * SS * EE;    // [B,S,S]

    __half *Xh, *Wh, *Qh, *Ath;
    cudaGetSymbolAddress((void**)&Xh, g_Xh);
    cudaGetSymbolAddress((void**)&Wh, g_Wh);
    cudaGetSymbolAddress((void**)&Qh, g_qkv_h);
    cudaGetSymbolAddress((void**)&Ath, g_attn_h);

    (void)cudaFuncSetAttribute(gemm_f16<0>,
        cudaFuncAttributeMaxDynamicSharedMemorySize, 2 * STAGE0);
    (void)cudaFuncSetAttribute(gemm_f16<1>,
        cudaFuncAttributeMaxDynamicSharedMemorySize, 2 * STAGE1);

    // 1) convert X and W to fp16
    cvt_f16<<<(BB * SS * EE / 4 + 255) / 256, 256>>>(
        (const float4*)X, Xh, (size_t)BB * SS * EE / 4);
    cvt_f16<<<(FF * EE / 4 + 255) / 256, 256>>>(
        (const float4*)W, Wh, (size_t)FF * EE / 4);

    // 2) qkv = X @ W^T + bias -> fp16  [8192,3072]
    gemm_f16<0><<<dim3(FF / 128, (BB * SS) / 128, 1), 256, 2 * STAGE0>>>(
        Xh, Wh,
        EE, EE, EE, FF,
        (size_t)0, (size_t)0, (size_t)0,
        0, 1.0f, nullptr, Qh, bias);

    // 3) scores = Q @ K^T / 32 -> fp32 attn slice
    gemm_f16<0><<<dim3(SS / 128, SS / 128, BB), 256, 2 * STAGE0>>>(
        Qh, Qh + EE,
        EE, FF, FF, SS,
        (size_t)SS * FF, (size_t)SS * FF, (size_t)SS * SS,
        1, 1.0f / 32.0f, attn, nullptr, nullptr);

    // 4) softmax rows (fp32 in place) + fp16 copy
    softmax_h<<<BB * SS, 256>>>(attn, Ath);

    // 5) out = attn @ V -> fp32  (V native [K][N] via ldmatrix.trans)
    gemm_f16<1><<<dim3(EE / 128, SS / 128, BB), 256, 2 * STAGE1>>>(
        Ath, Qh + 2 * EE,
        SS, SS, FF, EE,
        (size_t)SS * SS, (size_t)SS * FF, (size_t)SS * EE,
        1, 1.0f, out, nullptr, nullptr);
}